// round 6
// baseline (speedup 1.0000x reference)
#include <cuda_runtime.h>
#include <cuda_bf16.h>
#include <cstdint>

#define NPTS 8192
#define HSIZE (64*NPTS*64)      // [b][n][i] elems = 33.5M
typedef unsigned int u32; typedef unsigned short u16; typedef __nv_bfloat16 bf16;

// ---- device scratch ----
__device__ bf16 g_h0hi[HSIZE], g_h0lo[HSIZE], g_h1hi[HSIZE], g_h1lo[HSIZE];
__device__ bf16 g_bash[32*NPTS], g_basl[32*NPTS];    // [freq r][pos]  r<16 cos, r>=16 sin
__device__ bf16 g_basTh[NPTS*32], g_basTl[NPTS*32];  // [pos][r]
__device__ float g_Fp[8*4096*32];
__device__ float g_F[4096*32];                       // [b*64+i][0..15 cosS |16..31 sinS]
__device__ float g_G[64*2*16*64];                    // [b][re/im][k][o] scaled
__device__ u16 g_Ah[64*64*96], g_Al[64*64*96];       // per-batch A [o][96]

__device__ __forceinline__ float gelu_exact(float v){ return 0.5f*v*(1.0f+erff(v*0.7071067811865476f)); }
__device__ __forceinline__ void split_bf(float v, u16& h, u16& l){
    bf16 bh=__float2bfloat16(v); bf16 bl=__float2bfloat16(v-__bfloat162float(bh));
    h=__bfloat16_as_ushort(bh); l=__bfloat16_as_ushort(bl);
}
__device__ __forceinline__ void mma_bf16(float* d, const u32* a, u32 b0, u32 b1){
    asm volatile("mma.sync.aligned.m16n8k16.row.col.f32.bf16.bf16.f32 "
        "{%0,%1,%2,%3}, {%4,%5,%6,%7}, {%8,%9}, {%0,%1,%2,%3};"
        : "+f"(d[0]),"+f"(d[1]),"+f"(d[2]),"+f"(d[3])
        : "r"(a[0]),"r"(a[1]),"r"(a[2]),"r"(a[3]),"r"(b0),"r"(b1));
}

// ---- basis ----
__global__ void k_basis(){
    int idx=blockIdx.x*blockDim.x+threadIdx.x;       // 32*8192
    int r=idx>>13, n=idx&(NPTS-1), k=r&15;
    int rm=(k*n)&(NPTS-1);
    float a=(float)rm*(1.f/4096.f); float s,c; sincospif(a,&s,&c);
    float v=(r<16)?c:s;
    u16 hb,lb; split_bf(v,hb,lb);
    g_bash[r*NPTS+n]=__ushort_as_bfloat16(hb);  g_basl[r*NPTS+n]=__ushort_as_bfloat16(lb);
    g_basTh[n*32+r]=__ushort_as_bfloat16(hb);   g_basTl[n*32+r]=__ushort_as_bfloat16(lb);
}

// ---- lifting: h0[b][n][i] ----
__global__ void k_lift(const float* __restrict__ x, const float* __restrict__ pw,
                       const float* __restrict__ pb){
    int idx=blockIdx.x*blockDim.x+threadIdx.x;
    int b=idx>>19, n=(idx>>6)&(NPTS-1), i=idx&63;
    float v = x[(b<<13)|n]*pw[2*i] + ((float)n*(1.f/8191.f))*pw[2*i+1] + pb[i];
    u16 hb,lb; split_bf(v,hb,lb);
    g_h0hi[idx]=__ushort_as_bfloat16(hb); g_h0lo[idx]=__ushort_as_bfloat16(lb);
}

// ---- standalone forward DFT (layer 0 only): rows=(b,i) 128/CTA, N=32, K split 8x1024 ----
// smem(u16): A2 interleaved [64 pos-pair][272] x2 prec; B [32][136] x2
#define FW_A2H 0
#define FW_A2L 17408
#define FW_BH  34816
#define FW_BL  39168
__global__ void __launch_bounds__(128) k_fwd(const bf16* __restrict__ hhi, const bf16* __restrict__ hlo){
    extern __shared__ u16 smu[];
    const int tid=threadIdx.x, lane=tid&31, wid=tid>>5;
    const int gid=lane>>2, tid4=lane&3;
    const int mb=blockIdx.x, split=blockIdx.y;
    float acc[2][4][4];
#pragma unroll
    for(int a=0;a<2;a++) for(int b=0;b<4;b++) for(int c=0;c<4;c++) acc[a][b][c]=0.f;
    for(int ch=0;ch<8;ch++){
        int nwin=split*1024+ch*128;
        // stage A2 (transpose [n][i] -> [pos-pair][2m+q])
        for(int it=0;it<4;it++){
            int pp=it*16+(tid>>3), iblk=tid&7;
#pragma unroll
            for(int bl=0;bl<2;bl++){
                size_t base=((size_t)(mb*2+bl)*NPTS + nwin + pp*2)*64 + iblk*8;
                uint4 q0=*(const uint4*)(hhi+base); uint4 q1=*(const uint4*)(hhi+base+64);
                u16 e0[8],e1[8]; *(uint4*)e0=q0; *(uint4*)e1=q1;
                u32* dst=(u32*)(smu+FW_A2H)+pp*136+bl*64+iblk*8;
#pragma unroll
                for(int j=0;j<8;j++) dst[j]=(u32)e0[j]|((u32)e1[j]<<16);
                q0=*(const uint4*)(hlo+base); q1=*(const uint4*)(hlo+base+64);
                *(uint4*)e0=q0; *(uint4*)e1=q1;
                dst=(u32*)(smu+FW_A2L)+pp*136+bl*64+iblk*8;
#pragma unroll
                for(int j=0;j<8;j++) dst[j]=(u32)e0[j]|((u32)e1[j]<<16);
            }
        }
        for(int e=tid;e<512;e+=128){
            int f=e>>4, blk=e&15;
            *(uint4*)(smu+FW_BH+f*136+blk*8)=*(const uint4*)((const u16*)g_bash+f*NPTS+nwin+blk*8);
            *(uint4*)(smu+FW_BL+f*136+blk*8)=*(const uint4*)((const u16*)g_basl+f*NPTS+nwin+blk*8);
        }
        __syncthreads();
        const int m0=wid*32;
        const u32* A2h=(const u32*)(smu+FW_A2H);
        const u32* A2l=(const u32*)(smu+FW_A2L);
        for(int ks=0;ks<8;ks++){
            int k0=ks*16, p=k0/2+tid4;
            u32 ah[2][4], al[2][4];
#pragma unroll
            for(int mt=0;mt<2;mt++){
                int m=m0+mt*16+gid;
                ah[mt][0]=A2h[p*136+m];     ah[mt][1]=A2h[p*136+m+8];
                ah[mt][2]=A2h[(p+4)*136+m]; ah[mt][3]=A2h[(p+4)*136+m+8];
                al[mt][0]=A2l[p*136+m];     al[mt][1]=A2l[p*136+m+8];
                al[mt][2]=A2l[(p+4)*136+m]; al[mt][3]=A2l[(p+4)*136+m+8];
            }
#pragma unroll
            for(int nt=0;nt<4;nt++){
                int rb=(nt*8+gid)*136+k0+tid4*2;
                u32 bh0=*(const u32*)(smu+FW_BH+rb), bh1=*(const u32*)(smu+FW_BH+rb+8);
                u32 bl0=*(const u32*)(smu+FW_BL+rb), bl1=*(const u32*)(smu+FW_BL+rb+8);
#pragma unroll
                for(int mt=0;mt<2;mt++){
                    mma_bf16(acc[mt][nt],ah[mt],bh0,bh1);
                    mma_bf16(acc[mt][nt],ah[mt],bl0,bl1);
                    mma_bf16(acc[mt][nt],al[mt],bh0,bh1);
                }
            }
        }
        __syncthreads();
    }
#pragma unroll
    for(int mt=0;mt<2;mt++)
#pragma unroll
    for(int nt=0;nt<4;nt++){
        int row=mb*128+wid*32+mt*16+gid, col=nt*8+tid4*2;
        float* dp=g_Fp+(size_t)split*131072+row*32+col;
        *(float2*)dp=make_float2(acc[mt][nt][0],acc[mt][nt][1]);
        *(float2*)(dp+8*32)=make_float2(acc[mt][nt][2],acc[mt][nt][3]);
    }
}

__global__ void k_fred(){
    int idx=blockIdx.x*blockDim.x+threadIdx.x;
    float s=0.f;
#pragma unroll
    for(int p=0;p<8;p++) s+=g_Fp[p*131072+idx];
    g_F[idx]=s;
}
__global__ void k_zero(){ g_F[blockIdx.x*blockDim.x+threadIdx.x]=0.f; }

// ---- mode mix ----
__global__ void k_mix(const float* __restrict__ wr, const float* __restrict__ wi){
    __shared__ float Fs[64][32];
    const int b=blockIdx.x, tid=threadIdx.x;
#pragma unroll
    for(int t=0;t<8;t++){ int e=tid+t*256; Fs[e>>5][e&31]=g_F[b*2048+e]; }
    __syncthreads();
    const int k=tid&15, og=tid>>4;
#pragma unroll
    for(int rep=0;rep<4;rep++){
        int o=og+rep*16;
        float gre=0.f,gim=0.f;
#pragma unroll 8
        for(int i=0;i<64;i++){
            float fr=Fs[i][k], S=Fs[i][16+k];
            float wrv=wr[(i*64+o)*16+k], wiv=wi[(i*64+o)*16+k];
            gre+=fr*wrv+S*wiv; gim+=fr*wiv-S*wrv;
        }
        float sc=(k==0?1.0f:2.0f)*(1.0f/(float)NPTS);
        g_G[(b*2+0)*1024+k*64+o]=gre*sc;
        g_G[(b*2+1)*1024+k*64+o]=gim*sc;
    }
}

// ---- per-batch A = [W | Gr | -Gi]  [64 o][96 k] ----
__global__ void k_prepA(const float* __restrict__ ww){
    int b=blockIdx.x;
    for(int t=threadIdx.x;t<6144;t+=128){
        int o=t/96, c=t%96;
        float v;
        if(c<64) v=ww[o*64+c];
        else if(c<80) v= g_G[(b*2+0)*1024+(c-64)*64+o];
        else          v=-g_G[(b*2+1)*1024+(c-80)*64+o];
        u16 hb,lb; split_bf(v,hb,lb);
        g_Ah[b*6144+t]=hb; g_Al[b*6144+t]=lb;
    }
}

// ---- fused layer: D[64 o][128 n] = A[64x96]·BT, epilogue + fused next-F ----
// smem(u16): A[64][104]x2, BT[128][104]x2 ; epi reuse: bounce[128][72]x2, B2[32][136]x2
#define LA_AH 0
#define LA_AL 6656
#define LA_BTH 13312
#define LA_BTL 26624
#define LA_BNH 0
#define LA_BNL 9216
#define LA_B2H 18432
#define LA_B2L 22784
__global__ void __launch_bounds__(128) k_layer(const bf16* __restrict__ shi, const bf16* __restrict__ slo,
                                               bf16* __restrict__ dhi, bf16* __restrict__ dlo,
                                               const float* __restrict__ wb, int do_f){
    extern __shared__ u16 smu[];
    const int tid=threadIdx.x, lane=tid&31, wid=tid>>5;
    const int gid=lane>>2, tid4=lane&3;
    const int b=blockIdx.y, n0=blockIdx.x*128;
    {   // stage A
        const uint4* s0=(const uint4*)(g_Ah+b*6144);
        const uint4* s1=(const uint4*)(g_Al+b*6144);
        for(int e=tid;e<768;e+=128){
            int o=e/12, c=e%12;
            *(uint4*)(smu+LA_AH+o*104+c*8)=s0[e];
            *(uint4*)(smu+LA_AL+o*104+c*8)=s1[e];
        }
    }
    for(int e=tid;e<1024;e+=128){   // BT h part (cols 0..63)
        int n=e>>3, blk=e&7;
        size_t src=((size_t)b*NPTS+n0+n)*64+blk*8;
        *(uint4*)(smu+LA_BTH+n*104+blk*8)=*(const uint4*)(shi+src);
        *(uint4*)(smu+LA_BTL+n*104+blk*8)=*(const uint4*)(slo+src);
    }
    for(int e=tid;e<512;e+=128){    // BT basis part (cols 64..95)
        int n=e>>2, blk=e&3;
        *(uint4*)(smu+LA_BTH+n*104+64+blk*8)=*(const uint4*)((const u16*)g_basTh+(size_t)(n0+n)*32+blk*8);
        *(uint4*)(smu+LA_BTL+n*104+64+blk*8)=*(const uint4*)((const u16*)g_basTl+(size_t)(n0+n)*32+blk*8);
    }
    __syncthreads();
    const int m0=(wid&1)*32, nb0=(wid>>1)*64;
    float acc[2][8][4];
#pragma unroll
    for(int a=0;a<2;a++) for(int x=0;x<8;x++) for(int c=0;c<4;c++) acc[a][x][c]=0.f;
    for(int ks=0;ks<6;ks++){
        int k0=ks*16;
        u32 ah[2][4], al[2][4];
#pragma unroll
        for(int mt=0;mt<2;mt++){
            int r=(m0+mt*16+gid)*104+k0+tid4*2;
            ah[mt][0]=*(const u32*)(smu+LA_AH+r);       ah[mt][1]=*(const u32*)(smu+LA_AH+r+8*104);
            ah[mt][2]=*(const u32*)(smu+LA_AH+r+8);     ah[mt][3]=*(const u32*)(smu+LA_AH+r+8*104+8);
            al[mt][0]=*(const u32*)(smu+LA_AL+r);       al[mt][1]=*(const u32*)(smu+LA_AL+r+8*104);
            al[mt][2]=*(const u32*)(smu+LA_AL+r+8);     al[mt][3]=*(const u32*)(smu+LA_AL+r+8*104+8);
        }
#pragma unroll
        for(int nt=0;nt<8;nt++){
            int rb=(nb0+nt*8+gid)*104+k0+tid4*2;
            u32 bh0=*(const u32*)(smu+LA_BTH+rb), bh1=*(const u32*)(smu+LA_BTH+rb+8);
            u32 bl0=*(const u32*)(smu+LA_BTL+rb), bl1=*(const u32*)(smu+LA_BTL+rb+8);
#pragma unroll
            for(int mt=0;mt<2;mt++){
                mma_bf16(acc[mt][nt],ah[mt],bh0,bh1);
                mma_bf16(acc[mt][nt],ah[mt],bl0,bl1);
                mma_bf16(acc[mt][nt],al[mt],bh0,bh1);
            }
        }
    }
    __syncthreads();   // done reading A/BT; reuse smem
    // epilogue: bias + GELU + split -> bounce [n][72 o-pad]
#pragma unroll
    for(int mt=0;mt<2;mt++){
        int o0=m0+mt*16+gid, o1=o0+8;
        float b0=__ldg(wb+o0), b1=__ldg(wb+o1);
#pragma unroll
        for(int nt=0;nt<8;nt++){
            int n=nb0+nt*8+tid4*2;
            float v0=gelu_exact(acc[mt][nt][0]+b0), v1=gelu_exact(acc[mt][nt][1]+b0);
            float v2=gelu_exact(acc[mt][nt][2]+b1), v3=gelu_exact(acc[mt][nt][3]+b1);
            u16 h,l;
            split_bf(v0,h,l); smu[LA_BNH+n*72+o0]=h;     smu[LA_BNL+n*72+o0]=l;
            split_bf(v1,h,l); smu[LA_BNH+(n+1)*72+o0]=h; smu[LA_BNL+(n+1)*72+o0]=l;
            split_bf(v2,h,l); smu[LA_BNH+n*72+o1]=h;     smu[LA_BNL+n*72+o1]=l;
            split_bf(v3,h,l); smu[LA_BNH+(n+1)*72+o1]=h; smu[LA_BNL+(n+1)*72+o1]=l;
        }
    }
    if(do_f){   // stage basis rows for fused F-GEMM
        for(int e=tid;e<512;e+=128){
            int f=e>>4, blk=e&15;
            *(uint4*)(smu+LA_B2H+f*136+blk*8)=*(const uint4*)((const u16*)g_bash+(size_t)f*NPTS+n0+blk*8);
            *(uint4*)(smu+LA_B2L+f*136+blk*8)=*(const uint4*)((const u16*)g_basl+(size_t)f*NPTS+n0+blk*8);
        }
    }
    __syncthreads();
    // coalesced global write of h' [b][n][o]
    for(int e=tid;e<1024;e+=128){
        int n=e>>3, blk=e&7;
        size_t dst=((size_t)b*NPTS+n0+n)*64+blk*8;
        *(uint4*)(dhi+dst)=*(const uint4*)(smu+LA_BNH+n*72+blk*8);
        *(uint4*)(dlo+dst)=*(const uint4*)(smu+LA_BNL+n*72+blk*8);
    }
    if(do_f){   // partial F for next layer: F[o][freq] += sum_n h'[o][n]*bas[freq][n]
        const int mo=wid*16;
        float fa[4][4];
#pragma unroll
        for(int x=0;x<4;x++) for(int c=0;c<4;c++) fa[x][c]=0.f;
        for(int ks=0;ks<8;ks++){
            int k0=ks*16, c0=k0+tid4*2;
            u32 ah[4], al[4];
            int oA=mo+gid, oB=mo+gid+8;
            ah[0]=(u32)smu[LA_BNH+c0*72+oA]     | ((u32)smu[LA_BNH+(c0+1)*72+oA]<<16);
            ah[1]=(u32)smu[LA_BNH+c0*72+oB]     | ((u32)smu[LA_BNH+(c0+1)*72+oB]<<16);
            ah[2]=(u32)smu[LA_BNH+(c0+8)*72+oA] | ((u32)smu[LA_BNH+(c0+9)*72+oA]<<16);
            ah[3]=(u32)smu[LA_BNH+(c0+8)*72+oB] | ((u32)smu[LA_BNH+(c0+9)*72+oB]<<16);
            al[0]=(u32)smu[LA_BNL+c0*72+oA]     | ((u32)smu[LA_BNL+(c0+1)*72+oA]<<16);
            al[1]=(u32)smu[LA_BNL+c0*72+oB]     | ((u32)smu[LA_BNL+(c0+1)*72+oB]<<16);
            al[2]=(u32)smu[LA_BNL+(c0+8)*72+oA] | ((u32)smu[LA_BNL+(c0+9)*72+oA]<<16);
            al[3]=(u32)smu[LA_BNL+(c0+8)*72+oB] | ((u32)smu[LA_BNL+(c0+9)*72+oB]<<16);
#pragma unroll
            for(int nt=0;nt<4;nt++){
                int rb=(nt*8+gid)*136+k0+tid4*2;
                u32 bh0=*(const u32*)(smu+LA_B2H+rb), bh1=*(const u32*)(smu+LA_B2H+rb+8);
                u32 bl0=*(const u32*)(smu+LA_B2L+rb), bl1=*(const u32*)(smu+LA_B2L+rb+8);
                mma_bf16(fa[nt],ah,bh0,bh1);
                mma_bf16(fa[nt],ah,bl0,bl1);
                mma_bf16(fa[nt],al,bh0,bh1);
            }
        }
#pragma unroll
        for(int nt=0;nt<4;nt++){
            int col=nt*8+tid4*2;
            atomicAdd(&g_F[(b*64+mo+gid)*32+col],   fa[nt][0]);
            atomicAdd(&g_F[(b*64+mo+gid)*32+col+1], fa[nt][1]);
            atomicAdd(&g_F[(b*64+mo+gid+8)*32+col],   fa[nt][2]);
            atomicAdd(&g_F[(b*64+mo+gid+8)*32+col+1], fa[nt][3]);
        }
    }
}

// ---- projection: out[b*8192+n] = sum_i (hi+lo)*qw[i] + qb ----
__global__ void k_proj(const bf16* __restrict__ hhi, const bf16* __restrict__ hlo,
                       const float* __restrict__ qw, const float* __restrict__ qb,
                       float* __restrict__ out){
    int t=threadIdx.x;
    int r=blockIdx.x*32 + (t>>3);
    int l8=t&7;
    size_t base=(size_t)r*64 + l8*8;
    float acc=0.f;
    uint4 qh=*(const uint4*)(hhi+base); uint4 ql=*(const uint4*)(hlo+base);
    u16 eh[8],el[8]; *(uint4*)eh=qh; *(uint4*)el=ql;
#pragma unroll
    for(int j=0;j<8;j++)
        acc += (__bfloat162float(__ushort_as_bfloat16(eh[j]))+__bfloat162float(__ushort_as_bfloat16(el[j])))*__ldg(qw+l8*8+j);
    acc += __shfl_down_sync(0xFFFFFFFFu,acc,4);
    acc += __shfl_down_sync(0xFFFFFFFFu,acc,2);
    acc += __shfl_down_sync(0xFFFFFFFFu,acc,1);
    if(l8==0) out[r]=acc+__ldg(qb);
}

// ---- launch ----
extern "C" void kernel_launch(void* const* d_in, const int* in_sizes, int n_in,
                              void* d_out, int out_size){
    const float* x =(const float*)d_in[0];
    const float* pw=(const float*)d_in[1];
    const float* pb=(const float*)d_in[2];
    const float* wr=(const float*)d_in[3];
    const float* wi=(const float*)d_in[4];
    const float* ww=(const float*)d_in[5];
    const float* wb=(const float*)d_in[6];
    const float* qw=(const float*)d_in[7];
    const float* qb=(const float*)d_in[8];
    float* out=(float*)d_out;

    bf16 *h0h,*h0l,*h1h,*h1l;
    cudaGetSymbolAddress((void**)&h0h,g_h0hi); cudaGetSymbolAddress((void**)&h0l,g_h0lo);
    cudaGetSymbolAddress((void**)&h1h,g_h1hi); cudaGetSymbolAddress((void**)&h1l,g_h1lo);

    cudaFuncSetAttribute(k_fwd,  cudaFuncAttributeMaxDynamicSharedMemorySize, 87040);
    cudaFuncSetAttribute(k_layer,cudaFuncAttributeMaxDynamicSharedMemorySize, 79872);

    k_basis<<<1024,256>>>();
    k_lift<<<HSIZE/256,256>>>(x,pw,pb);
    k_fwd<<<dim3(32,8),128,87040>>>(h0h,h0l);
    k_fred<<<512,256>>>();

    const bf16 *shi=h0h,*slo=h0l; bf16 *dhi=h1h,*dlo=h1l;
    for(int l=0;l<4;l++){
        k_mix<<<64,256>>>(wr+l*65536, wi+l*65536);
        k_prepA<<<64,128>>>(ww+l*4096);
        if(l<3) k_zero<<<512,256>>>();
        k_layer<<<dim3(64,64),128,79872>>>(shi,slo,dhi,dlo,wb+l*64,(l<3)?1:0);
        const bf16* th=shi; const bf16* tl=slo;
        shi=dhi; slo=dlo; dhi=(bf16*)th; dlo=(bf16*)tl;
    }
    k_proj<<<16384,256>>>(shi,slo,qw,qb,out);
}

// round 9
// speedup vs baseline: 1.1509x; 1.1509x over previous
#include <cuda_runtime.h>
#include <cuda_bf16.h>
#include <cstdint>

#define NPTS 8192
#define HSIZE (64*NPTS*64)      // [b][n][i] elems = 33.5M
typedef unsigned int u32; typedef unsigned short u16; typedef __nv_bfloat16 bf16;

// ---- device scratch ----
__device__ bf16 g_h0hi[HSIZE], g_h0lo[HSIZE], g_h1hi[HSIZE], g_h1lo[HSIZE];
__device__ bf16 g_bash[32*NPTS], g_basl[32*NPTS];    // [freq r][pos]  r<16 cos, r>=16 sin
__device__ bf16 g_basTh[NPTS*32], g_basTl[NPTS*32];  // [pos][r]
__device__ u32 g_basPh[4096*32], g_basPl[4096*32];   // packed pairs [n/2][r]: (bf16(n),bf16(n+1))
__device__ float g_Fp[8*4096*32];
__device__ float g_F[4096*32];                       // [b*64+i][0..15 cosS |16..31 sinS]
__device__ float g_G[64*2*16*64];                    // [b][re/im][k][o] scaled
__device__ u16 g_Ah[64*64*96], g_Al[64*64*96];       // per-batch A [o][96]

__device__ __forceinline__ float gelu_exact(float v){ return 0.5f*v*(1.0f+erff(v*0.7071067811865476f)); }
__device__ __forceinline__ void split_bf(float v, u16& h, u16& l){
    bf16 bh=__float2bfloat16(v); bf16 bl=__float2bfloat16(v-__bfloat162float(bh));
    h=__bfloat16_as_ushort(bh); l=__bfloat16_as_ushort(bl);
}
__device__ __forceinline__ void mma_bf16(float* d, const u32* a, u32 b0, u32 b1){
    asm volatile("mma.sync.aligned.m16n8k16.row.col.f32.bf16.bf16.f32 "
        "{%0,%1,%2,%3}, {%4,%5,%6,%7}, {%8,%9}, {%0,%1,%2,%3};"
        : "+f"(d[0]),"+f"(d[1]),"+f"(d[2]),"+f"(d[3])
        : "r"(a[0]),"r"(a[1]),"r"(a[2]),"r"(a[3]),"r"(b0),"r"(b1));
}

// ---- basis (pairs) ----
__global__ void k_basis(){
    int idx=blockIdx.x*blockDim.x+threadIdx.x;       // < 32*4096
    int r=idx>>12, np=idx&4095, k=r&15;
    u16 hh[2], ll[2];
#pragma unroll
    for(int q=0;q<2;q++){
        int n=2*np+q;
        int rm=(k*n)&(NPTS-1);
        float a=(float)rm*(1.f/4096.f); float s,c; sincospif(a,&s,&c);
        float v=(r<16)?c:s;
        split_bf(v,hh[q],ll[q]);
        g_bash[r*NPTS+n]=__ushort_as_bfloat16(hh[q]);  g_basl[r*NPTS+n]=__ushort_as_bfloat16(ll[q]);
        g_basTh[n*32+r]=__ushort_as_bfloat16(hh[q]);   g_basTl[n*32+r]=__ushort_as_bfloat16(ll[q]);
    }
    g_basPh[np*32+r]=(u32)hh[0]|((u32)hh[1]<<16);
    g_basPl[np*32+r]=(u32)ll[0]|((u32)ll[1]<<16);
}

// ---- lifting: h0[b][n][i] ----
__global__ void k_lift(const float* __restrict__ x, const float* __restrict__ pw,
                       const float* __restrict__ pb){
    int idx=blockIdx.x*blockDim.x+threadIdx.x;
    int b=idx>>19, n=(idx>>6)&(NPTS-1), i=idx&63;
    float v = x[(b<<13)|n]*pw[2*i] + ((float)n*(1.f/8191.f))*pw[2*i+1] + pb[i];
    u16 hb,lb; split_bf(v,hb,lb);
    g_h0hi[idx]=__ushort_as_bfloat16(hb); g_h0lo[idx]=__ushort_as_bfloat16(lb);
}

// ---- standalone forward DFT (layer 0 only) ----
#define FW_A2H 0
#define FW_A2L 17408
#define FW_BH  34816
#define FW_BL  39168
__global__ void __launch_bounds__(128) k_fwd(const bf16* __restrict__ hhi, const bf16* __restrict__ hlo){
    extern __shared__ u16 smu[];
    const int tid=threadIdx.x, lane=tid&31, wid=tid>>5;
    const int gid=lane>>2, tid4=lane&3;
    const int mb=blockIdx.x, split=blockIdx.y;
    float acc[2][4][4];
#pragma unroll
    for(int a=0;a<2;a++) for(int b=0;b<4;b++) for(int c=0;c<4;c++) acc[a][b][c]=0.f;
    for(int ch=0;ch<8;ch++){
        int nwin=split*1024+ch*128;
        for(int it=0;it<4;it++){
            int pp=it*16+(tid>>3), iblk=tid&7;
#pragma unroll
            for(int bl=0;bl<2;bl++){
                size_t base=((size_t)(mb*2+bl)*NPTS + nwin + pp*2)*64 + iblk*8;
                uint4 q0=*(const uint4*)(hhi+base); uint4 q1=*(const uint4*)(hhi+base+64);
                u16 e0[8],e1[8]; *(uint4*)e0=q0; *(uint4*)e1=q1;
                u32* dst=(u32*)(smu+FW_A2H)+pp*136+bl*64+iblk*8;
#pragma unroll
                for(int j=0;j<8;j++) dst[j]=(u32)e0[j]|((u32)e1[j]<<16);
                q0=*(const uint4*)(hlo+base); q1=*(const uint4*)(hlo+base+64);
                *(uint4*)e0=q0; *(uint4*)e1=q1;
                dst=(u32*)(smu+FW_A2L)+pp*136+bl*64+iblk*8;
#pragma unroll
                for(int j=0;j<8;j++) dst[j]=(u32)e0[j]|((u32)e1[j]<<16);
            }
        }
        for(int e=tid;e<512;e+=128){
            int f=e>>4, blk=e&15;
            *(uint4*)(smu+FW_BH+f*136+blk*8)=*(const uint4*)((const u16*)g_bash+f*NPTS+nwin+blk*8);
            *(uint4*)(smu+FW_BL+f*136+blk*8)=*(const uint4*)((const u16*)g_basl+f*NPTS+nwin+blk*8);
        }
        __syncthreads();
        const int m0=wid*32;
        const u32* A2h=(const u32*)(smu+FW_A2H);
        const u32* A2l=(const u32*)(smu+FW_A2L);
        for(int ks=0;ks<8;ks++){
            int k0=ks*16, p=k0/2+tid4;
            u32 ah[2][4], al[2][4];
#pragma unroll
            for(int mt=0;mt<2;mt++){
                int m=m0+mt*16+gid;
                ah[mt][0]=A2h[p*136+m];     ah[mt][1]=A2h[p*136+m+8];
                ah[mt][2]=A2h[(p+4)*136+m]; ah[mt][3]=A2h[(p+4)*136+m+8];
                al[mt][0]=A2l[p*136+m];     al[mt][1]=A2l[p*136+m+8];
                al[mt][2]=A2l[(p+4)*136+m]; al[mt][3]=A2l[(p+4)*136+m+8];
            }
#pragma unroll
            for(int nt=0;nt<4;nt++){
                int rb=(nt*8+gid)*136+k0+tid4*2;
                u32 bh0=*(const u32*)(smu+FW_BH+rb), bh1=*(const u32*)(smu+FW_BH+rb+8);
                u32 bl0=*(const u32*)(smu+FW_BL+rb), bl1=*(const u32*)(smu+FW_BL+rb+8);
#pragma unroll
                for(int mt=0;mt<2;mt++){
                    mma_bf16(acc[mt][nt],ah[mt],bh0,bh1);
                    mma_bf16(acc[mt][nt],ah[mt],bl0,bl1);
                    mma_bf16(acc[mt][nt],al[mt],bh0,bh1);
                }
            }
        }
        __syncthreads();
    }
#pragma unroll
    for(int mt=0;mt<2;mt++)
#pragma unroll
    for(int nt=0;nt<4;nt++){
        int row=mb*128+wid*32+mt*16+gid, col=nt*8+tid4*2;
        float* dp=g_Fp+(size_t)split*131072+row*32+col;
        *(float2*)dp=make_float2(acc[mt][nt][0],acc[mt][nt][1]);
        *(float2*)(dp+8*32)=make_float2(acc[mt][nt][2],acc[mt][nt][3]);
    }
}

__global__ void k_fred(){
    int idx=blockIdx.x*blockDim.x+threadIdx.x;
    float s=0.f;
#pragma unroll
    for(int p=0;p<8;p++) s+=g_Fp[p*131072+idx];
    g_F[idx]=s;
}
__global__ void k_zero(){ g_F[blockIdx.x*blockDim.x+threadIdx.x]=0.f; }

// ---- mode mix ----
__global__ void k_mix(const float* __restrict__ wr, const float* __restrict__ wi){
    __shared__ float Fs[64][32];
    const int b=blockIdx.x, tid=threadIdx.x;
#pragma unroll
    for(int t=0;t<8;t++){ int e=tid+t*256; Fs[e>>5][e&31]=g_F[b*2048+e]; }
    __syncthreads();
    const int k=tid&15, og=tid>>4;
#pragma unroll
    for(int rep=0;rep<4;rep++){
        int o=og+rep*16;
        float gre=0.f,gim=0.f;
#pragma unroll 8
        for(int i=0;i<64;i++){
            float fr=Fs[i][k], S=Fs[i][16+k];
            float wrv=wr[(i*64+o)*16+k], wiv=wi[(i*64+o)*16+k];
            gre+=fr*wrv+S*wiv; gim+=fr*wiv-S*wrv;
        }
        float sc=(k==0?1.0f:2.0f)*(1.0f/(float)NPTS);
        g_G[(b*2+0)*1024+k*64+o]=gre*sc;
        g_G[(b*2+1)*1024+k*64+o]=gim*sc;
    }
}

// ---- per-batch A = [W | Gr | -Gi]  [64 o][96 k] ----
__global__ void k_prepA(const float* __restrict__ ww){
    int b=blockIdx.x;
    for(int t=threadIdx.x;t<6144;t+=128){
        int o=t/96, c=t%96;
        float v;
        if(c<64) v=ww[o*64+c];
        else if(c<80) v= g_G[(b*2+0)*1024+(c-64)*64+o];
        else          v=-g_G[(b*2+1)*1024+(c-80)*64+o];
        u16 hb,lb; split_bf(v,hb,lb);
        g_Ah[b*6144+t]=hb; g_Al[b*6144+t]=lb;
    }
}

// ---- fused layer, 256 threads: D[64 o][128 n] = A[64x96]·BT; epilogue + register-direct F ----
#define LA_AH 0
#define LA_AL 6656
#define LA_BTH 13312
#define LA_BTL 26624
#define EP_BNH 0
#define EP_BNL 9216
#define EP_B2H32 9216
#define EP_B2L32 11520
__global__ void __launch_bounds__(256) k_layer(const bf16* __restrict__ shi, const bf16* __restrict__ slo,
                                               bf16* __restrict__ dhi, bf16* __restrict__ dlo,
                                               const float* __restrict__ wb, int do_f){
    extern __shared__ __align__(16) u16 smu[];
    u32* smw=(u32*)smu;
    const int tid=threadIdx.x, lane=tid&31, wid=tid>>5;
    const int gid=lane>>2, tid4=lane&3;
    const int b=blockIdx.y, n0=blockIdx.x*128;
    {   // stage A
        const uint4* s0=(const uint4*)(g_Ah+b*6144);
        const uint4* s1=(const uint4*)(g_Al+b*6144);
        for(int e=tid;e<768;e+=256){
            int o=e/12, c=e%12;
            *(uint4*)(smu+LA_AH+o*104+c*8)=s0[e];
            *(uint4*)(smu+LA_AL+o*104+c*8)=s1[e];
        }
    }
    for(int e=tid;e<1024;e+=256){   // BT h part (k 0..63)
        int n=e>>3, blk=e&7;
        size_t src=((size_t)b*NPTS+n0+n)*64+blk*8;
        *(uint4*)(smu+LA_BTH+n*104+blk*8)=*(const uint4*)(shi+src);
        *(uint4*)(smu+LA_BTL+n*104+blk*8)=*(const uint4*)(slo+src);
    }
    for(int e=tid;e<512;e+=256){    // BT basis part (k 64..95)
        int n=e>>2, blk=e&3;
        *(uint4*)(smu+LA_BTH+n*104+64+blk*8)=*(const uint4*)((const u16*)g_basTh+(size_t)(n0+n)*32+blk*8);
        *(uint4*)(smu+LA_BTL+n*104+64+blk*8)=*(const uint4*)((const u16*)g_basTl+(size_t)(n0+n)*32+blk*8);
    }
    __syncthreads();
    const int m0=(wid&3)*16, nb0=(wid>>2)*64;
    float acc[8][4];
#pragma unroll
    for(int x=0;x<8;x++) for(int c=0;c<4;c++) acc[x][c]=0.f;
    for(int ks=0;ks<6;ks++){
        int k0=ks*16;
        u32 ah[4], al[4];
        int rA=(m0+gid)*104+k0+tid4*2;
        ah[0]=*(const u32*)(smu+LA_AH+rA);   ah[1]=*(const u32*)(smu+LA_AH+rA+8*104);
        ah[2]=*(const u32*)(smu+LA_AH+rA+8); ah[3]=*(const u32*)(smu+LA_AH+rA+8*104+8);
        al[0]=*(const u32*)(smu+LA_AL+rA);   al[1]=*(const u32*)(smu+LA_AL+rA+8*104);
        al[2]=*(const u32*)(smu+LA_AL+rA+8); al[3]=*(const u32*)(smu+LA_AL+rA+8*104+8);
#pragma unroll
        for(int nt=0;nt<8;nt++){
            int rb=(nb0+nt*8+gid)*104+k0+tid4*2;
            u32 bh0=*(const u32*)(smu+LA_BTH+rb), bh1=*(const u32*)(smu+LA_BTH+rb+8);
            u32 bl0=*(const u32*)(smu+LA_BTL+rb), bl1=*(const u32*)(smu+LA_BTL+rb+8);
            mma_bf16(acc[nt],ah,bh0,bh1);
            mma_bf16(acc[nt],ah,bl0,bl1);
            mma_bf16(acc[nt],al,bh0,bh1);
        }
    }
    __syncthreads();   // reuse smem
    if(do_f){   // stage packed-pair basis [64 np][36] u32 (conflict-free stride)
        for(int e=tid;e<2048;e+=256){
            int np=e>>5, rr=e&31;
            smw[EP_B2H32+np*36+rr]=g_basPh[((n0>>1)+np)*32+rr];
            smw[EP_B2L32+np*36+rr]=g_basPl[((n0>>1)+np)*32+rr];
        }
    }
    // epilogue: bias + GELU + split; bounce + register packs for F
    const int o0=m0+gid, o1=o0+8;
    float bb0=__ldg(wb+o0), bb1=__ldg(wb+o1);
    u32 ph[8],pl[8],qh[8],ql[8];
#pragma unroll
    for(int nt=0;nt<8;nt++){
        int n=nb0+nt*8+tid4*2;
        float v0=gelu_exact(acc[nt][0]+bb0), v1=gelu_exact(acc[nt][1]+bb0);
        float v2=gelu_exact(acc[nt][2]+bb1), v3=gelu_exact(acc[nt][3]+bb1);
        u16 h0,l0,h1,l1,h2,l2,h3,l3;
        split_bf(v0,h0,l0); split_bf(v1,h1,l1); split_bf(v2,h2,l2); split_bf(v3,h3,l3);
        smu[EP_BNH+n*72+o0]=h0; smu[EP_BNH+(n+1)*72+o0]=h1;
        smu[EP_BNH+n*72+o1]=h2; smu[EP_BNH+(n+1)*72+o1]=h3;
        smu[EP_BNL+n*72+o0]=l0; smu[EP_BNL+(n+1)*72+o0]=l1;
        smu[EP_BNL+n*72+o1]=l2; smu[EP_BNL+(n+1)*72+o1]=l3;
        ph[nt]=(u32)h0|((u32)h1<<16); pl[nt]=(u32)l0|((u32)l1<<16);
        qh[nt]=(u32)h2|((u32)h3<<16); ql[nt]=(u32)l2|((u32)l3<<16);
    }
    __syncthreads();
    for(int e=tid;e<1024;e+=256){   // coalesced global write [b][n][o]
        int n=e>>3, blk=e&7;
        size_t dst=((size_t)b*NPTS+n0+n)*64+blk*8;
        *(uint4*)(dhi+dst)=*(const uint4*)(smu+EP_BNH+n*72+blk*8);
        *(uint4*)(dlo+dst)=*(const uint4*)(smu+EP_BNL+n*72+blk*8);
    }
    if(do_f){   // F[o][freq] += h'·bas over this warp's n-slice, A operand from registers
        float fa[4][4];
#pragma unroll
        for(int x=0;x<4;x++) for(int c=0;c<4;c++) fa[x][c]=0.f;
#pragma unroll
        for(int ks=0;ks<4;ks++){
            u32 aFh[4]={ph[2*ks],qh[2*ks],ph[2*ks+1],qh[2*ks+1]};
            u32 aFl[4]={pl[2*ks],ql[2*ks],pl[2*ks+1],ql[2*ks+1]};
            int npb=(nb0>>1)+ks*8+tid4;
#pragma unroll
            for(int ft=0;ft<4;ft++){
                u32 bh0=smw[EP_B2H32+npb*36+ft*8+gid];
                u32 bh1=smw[EP_B2H32+(npb+4)*36+ft*8+gid];
                u32 bl0=smw[EP_B2L32+npb*36+ft*8+gid];
                u32 bl1=smw[EP_B2L32+(npb+4)*36+ft*8+gid];
                mma_bf16(fa[ft],aFh,bh0,bh1);
                mma_bf16(fa[ft],aFh,bl0,bl1);
                mma_bf16(fa[ft],aFl,bh0,bh1);
            }
        }
#pragma unroll
        for(int ft=0;ft<4;ft++){
            int col=ft*8+tid4*2;
            atomicAdd(&g_F[(b*64+o0)*32+col],   fa[ft][0]);
            atomicAdd(&g_F[(b*64+o0)*32+col+1], fa[ft][1]);
            atomicAdd(&g_F[(b*64+o1)*32+col],   fa[ft][2]);
            atomicAdd(&g_F[(b*64+o1)*32+col+1], fa[ft][3]);
        }
    }
}

// ---- projection ----
__global__ void k_proj(const bf16* __restrict__ hhi, const bf16* __restrict__ hlo,
                       const float* __restrict__ qw, const float* __restrict__ qb,
                       float* __restrict__ out){
    int t=threadIdx.x;
    int r=blockIdx.x*32 + (t>>3);
    int l8=t&7;
    size_t base=(size_t)r*64 + l8*8;
    float acc=0.f;
    uint4 qh=*(const uint4*)(hhi+base); uint4 ql=*(const uint4*)(hlo+base);
    u16 eh[8],el[8]; *(uint4*)eh=qh; *(uint4*)el=ql;
#pragma unroll
    for(int j=0;j<8;j++)
        acc += (__bfloat162float(__ushort_as_bfloat16(eh[j]))+__bfloat162float(__ushort_as_bfloat16(el[j])))*__ldg(qw+l8*8+j);
    acc += __shfl_down_sync(0xFFFFFFFFu,acc,4);
    acc += __shfl_down_sync(0xFFFFFFFFu,acc,2);
    acc += __shfl_down_sync(0xFFFFFFFFu,acc,1);
    if(l8==0) out[r]=acc+__ldg(qb);
}

// ---- launch ----
extern "C" void kernel_launch(void* const* d_in, const int* in_sizes, int n_in,
                              void* d_out, int out_size){
    const float* x =(const float*)d_in[0];
    const float* pw=(const float*)d_in[1];
    const float* pb=(const float*)d_in[2];
    const float* wr=(const float*)d_in[3];
    const float* wi=(const float*)d_in[4];
    const float* ww=(const float*)d_in[5];
    const float* wb=(const float*)d_in[6];
    const float* qw=(const float*)d_in[7];
    const float* qb=(const float*)d_in[8];
    float* out=(float*)d_out;

    bf16 *h0h,*h0l,*h1h,*h1l;
    cudaGetSymbolAddress((void**)&h0h,g_h0hi); cudaGetSymbolAddress((void**)&h0l,g_h0lo);
    cudaGetSymbolAddress((void**)&h1h,g_h1hi); cudaGetSymbolAddress((void**)&h1l,g_h1lo);

    cudaFuncSetAttribute(k_fwd,  cudaFuncAttributeMaxDynamicSharedMemorySize, 87040);
    cudaFuncSetAttribute(k_layer,cudaFuncAttributeMaxDynamicSharedMemorySize, 79872);

    k_basis<<<512,256>>>();
    k_lift<<<HSIZE/256,256>>>(x,pw,pb);
    k_fwd<<<dim3(32,8),128,87040>>>(h0h,h0l);
    k_fred<<<512,256>>>();

    const bf16 *shi=h0h,*slo=h0l; bf16 *dhi=h1h,*dlo=h1l;
    for(int l=0;l<4;l++){
        k_mix<<<64,256>>>(wr+l*65536, wi+l*65536);
        k_prepA<<<64,128>>>(ww+l*4096);
        if(l<3) k_zero<<<512,256>>>();
        k_layer<<<dim3(64,64),256,79872>>>(shi,slo,dhi,dlo,wb+l*64,(l<3)?1:0);
        const bf16* th=shi; const bf16* tl=slo;
        shi=dhi; slo=dlo; dhi=(bf16*)th; dlo=(bf16*)tl;
    }
    k_proj<<<16384,256>>>(shi,slo,qw,qb,out);
}

// round 10
// speedup vs baseline: 1.1759x; 1.0217x over previous
#include <cuda_runtime.h>
#include <cuda_bf16.h>
#include <cstdint>

#define NPTS 8192
#define HSIZE (64*NPTS*64)      // [b][n][i] elems = 33.5M
typedef unsigned int u32; typedef unsigned short u16; typedef __nv_bfloat16 bf16;

// ---- device scratch ----
__device__ bf16 g_h0hi[HSIZE], g_h0lo[HSIZE], g_h1hi[HSIZE], g_h1lo[HSIZE];
__device__ bf16 g_bash[32*NPTS], g_basl[32*NPTS];    // [freq r][pos]  r<16 cos, r>=16 sin
__device__ bf16 g_basTh[NPTS*32], g_basTl[NPTS*32];  // [pos][r]
__device__ float g_Fp[8*4096*32];
__device__ float g_F[4096*32];                       // [b*64+i][0..15 cosS |16..31 sinS]
__device__ float g_G[64*2*16*64];                    // [b][re/im][k][o] scaled
__device__ u16 g_Ah[64*64*96], g_Al[64*64*96];       // per-batch A [o][96]

__device__ __forceinline__ float gelu_exact(float v){ return 0.5f*v*(1.0f+erff(v*0.7071067811865476f)); }
__device__ __forceinline__ void split_bf(float v, u16& h, u16& l){
    bf16 bh=__float2bfloat16(v); bf16 bl=__float2bfloat16(v-__bfloat162float(bh));
    h=__bfloat16_as_ushort(bh); l=__bfloat16_as_ushort(bl);
}
__device__ __forceinline__ void mma_bf16(float* d, const u32* a, u32 b0, u32 b1){
    asm volatile("mma.sync.aligned.m16n8k16.row.col.f32.bf16.bf16.f32 "
        "{%0,%1,%2,%3}, {%4,%5,%6,%7}, {%8,%9}, {%0,%1,%2,%3};"
        : "+f"(d[0]),"+f"(d[1]),"+f"(d[2]),"+f"(d[3])
        : "r"(a[0]),"r"(a[1]),"r"(a[2]),"r"(a[3]),"r"(b0),"r"(b1));
}

// ---- basis ----
__global__ void k_basis(){
    int idx=blockIdx.x*blockDim.x+threadIdx.x;       // < 32*8192
    int r=idx>>13, n=idx&(NPTS-1), k=r&15;
    int rm=(k*n)&(NPTS-1);
    float a=(float)rm*(1.f/4096.f); float s,c; sincospif(a,&s,&c);
    float v=(r<16)?c:s;
    u16 hb,lb; split_bf(v,hb,lb);
    g_bash[r*NPTS+n]=__ushort_as_bfloat16(hb);  g_basl[r*NPTS+n]=__ushort_as_bfloat16(lb);
    g_basTh[n*32+r]=__ushort_as_bfloat16(hb);   g_basTl[n*32+r]=__ushort_as_bfloat16(lb);
}

// ---- lifting: h0[b][n][i] ----
__global__ void k_lift(const float* __restrict__ x, const float* __restrict__ pw,
                       const float* __restrict__ pb){
    int idx=blockIdx.x*blockDim.x+threadIdx.x;
    int b=idx>>19, n=(idx>>6)&(NPTS-1), i=idx&63;
    float v = x[(b<<13)|n]*pw[2*i] + ((float)n*(1.f/8191.f))*pw[2*i+1] + pb[i];
    u16 hb,lb; split_bf(v,hb,lb);
    g_h0hi[idx]=__ushort_as_bfloat16(hb); g_h0lo[idx]=__ushort_as_bfloat16(lb);
}

// ---- forward DFT (runs once per layer): rows=(b,i) 128/CTA, N=32, K split 8x1024 ----
#define FW_A2H 0
#define FW_A2L 17408
#define FW_BH  34816
#define FW_BL  39168
__global__ void __launch_bounds__(128) k_fwd(const bf16* __restrict__ hhi, const bf16* __restrict__ hlo){
    extern __shared__ u16 smu[];
    const int tid=threadIdx.x, lane=tid&31, wid=tid>>5;
    const int gid=lane>>2, tid4=lane&3;
    const int mb=blockIdx.x, split=blockIdx.y;
    float acc[2][4][4];
#pragma unroll
    for(int a=0;a<2;a++) for(int b=0;b<4;b++) for(int c=0;c<4;c++) acc[a][b][c]=0.f;
    for(int ch=0;ch<8;ch++){
        int nwin=split*1024+ch*128;
        for(int it=0;it<4;it++){
            int pp=it*16+(tid>>3), iblk=tid&7;
#pragma unroll
            for(int bl=0;bl<2;bl++){
                size_t base=((size_t)(mb*2+bl)*NPTS + nwin + pp*2)*64 + iblk*8;
                uint4 q0=*(const uint4*)(hhi+base); uint4 q1=*(const uint4*)(hhi+base+64);
                u16 e0[8],e1[8]; *(uint4*)e0=q0; *(uint4*)e1=q1;
                u32* dst=(u32*)(smu+FW_A2H)+pp*136+bl*64+iblk*8;
#pragma unroll
                for(int j=0;j<8;j++) dst[j]=(u32)e0[j]|((u32)e1[j]<<16);
                q0=*(const uint4*)(hlo+base); q1=*(const uint4*)(hlo+base+64);
                *(uint4*)e0=q0; *(uint4*)e1=q1;
                dst=(u32*)(smu+FW_A2L)+pp*136+bl*64+iblk*8;
#pragma unroll
                for(int j=0;j<8;j++) dst[j]=(u32)e0[j]|((u32)e1[j]<<16);
            }
        }
        for(int e=tid;e<512;e+=128){
            int f=e>>4, blk=e&15;
            *(uint4*)(smu+FW_BH+f*136+blk*8)=*(const uint4*)((const u16*)g_bash+f*NPTS+nwin+blk*8);
            *(uint4*)(smu+FW_BL+f*136+blk*8)=*(const uint4*)((const u16*)g_basl+f*NPTS+nwin+blk*8);
        }
        __syncthreads();
        const int m0=wid*32;
        const u32* A2h=(const u32*)(smu+FW_A2H);
        const u32* A2l=(const u32*)(smu+FW_A2L);
        for(int ks=0;ks<8;ks++){
            int k0=ks*16, p=k0/2+tid4;
            u32 ah[2][4], al[2][4];
#pragma unroll
            for(int mt=0;mt<2;mt++){
                int m=m0+mt*16+gid;
                ah[mt][0]=A2h[p*136+m];     ah[mt][1]=A2h[p*136+m+8];
                ah[mt][2]=A2h[(p+4)*136+m]; ah[mt][3]=A2h[(p+4)*136+m+8];
                al[mt][0]=A2l[p*136+m];     al[mt][1]=A2l[p*136+m+8];
                al[mt][2]=A2l[(p+4)*136+m]; al[mt][3]=A2l[(p+4)*136+m+8];
            }
#pragma unroll
            for(int nt=0;nt<4;nt++){
                int rb=(nt*8+gid)*136+k0+tid4*2;
                u32 bh0=*(const u32*)(smu+FW_BH+rb), bh1=*(const u32*)(smu+FW_BH+rb+8);
                u32 bl0=*(const u32*)(smu+FW_BL+rb), bl1=*(const u32*)(smu+FW_BL+rb+8);
#pragma unroll
                for(int mt=0;mt<2;mt++){
                    mma_bf16(acc[mt][nt],ah[mt],bh0,bh1);
                    mma_bf16(acc[mt][nt],ah[mt],bl0,bl1);
                    mma_bf16(acc[mt][nt],al[mt],bh0,bh1);
                }
            }
        }
        __syncthreads();
    }
#pragma unroll
    for(int mt=0;mt<2;mt++)
#pragma unroll
    for(int nt=0;nt<4;nt++){
        int row=mb*128+wid*32+mt*16+gid, col=nt*8+tid4*2;
        float* dp=g_Fp+(size_t)split*131072+row*32+col;
        *(float2*)dp=make_float2(acc[mt][nt][0],acc[mt][nt][1]);
        *(float2*)(dp+8*32)=make_float2(acc[mt][nt][2],acc[mt][nt][3]);
    }
}

__global__ void k_fred(){
    int idx=blockIdx.x*blockDim.x+threadIdx.x;
    float s=0.f;
#pragma unroll
    for(int p=0;p<8;p++) s+=g_Fp[p*131072+idx];
    g_F[idx]=s;
}

// ---- mode mix ----
__global__ void k_mix(const float* __restrict__ wr, const float* __restrict__ wi){
    __shared__ float Fs[64][32];
    const int b=blockIdx.x, tid=threadIdx.x;
#pragma unroll
    for(int t=0;t<8;t++){ int e=tid+t*256; Fs[e>>5][e&31]=g_F[b*2048+e]; }
    __syncthreads();
    const int k=tid&15, og=tid>>4;
#pragma unroll
    for(int rep=0;rep<4;rep++){
        int o=og+rep*16;
        float gre=0.f,gim=0.f;
#pragma unroll 8
        for(int i=0;i<64;i++){
            float fr=Fs[i][k], S=Fs[i][16+k];
            float wrv=wr[(i*64+o)*16+k], wiv=wi[(i*64+o)*16+k];
            gre+=fr*wrv+S*wiv; gim+=fr*wiv-S*wrv;
        }
        float sc=(k==0?1.0f:2.0f)*(1.0f/(float)NPTS);
        g_G[(b*2+0)*1024+k*64+o]=gre*sc;
        g_G[(b*2+1)*1024+k*64+o]=gim*sc;
    }
}

// ---- per-batch A = [W | Gr | -Gi]  [64 o][96 k] ----
__global__ void k_prepA(const float* __restrict__ ww){
    int b=blockIdx.x;
    for(int t=threadIdx.x;t<6144;t+=128){
        int o=t/96, c=t%96;
        float v;
        if(c<64) v=ww[o*64+c];
        else if(c<80) v= g_G[(b*2+0)*1024+(c-64)*64+o];
        else          v=-g_G[(b*2+1)*1024+(c-80)*64+o];
        u16 hb,lb; split_bf(v,hb,lb);
        g_Ah[b*6144+t]=hb; g_Al[b*6144+t]=lb;
    }
}

// ---- lean layer, 512 threads: D[64 o][128 n] = A[64x96]·BT; bias+GELU+split+store ----
#define LA_AH 0
#define LA_AL 6656
#define LA_BTH 13312
#define LA_BTL 26624
#define EP_BNH 0
#define EP_BNL 9216
__global__ void __launch_bounds__(512,2) k_layer(const bf16* __restrict__ shi, const bf16* __restrict__ slo,
                                                 bf16* __restrict__ dhi, bf16* __restrict__ dlo,
                                                 const float* __restrict__ wb){
    extern __shared__ __align__(16) u16 smu[];
    const int tid=threadIdx.x, lane=tid&31, wid=tid>>5;
    const int gid=lane>>2, tid4=lane&3;
    const int b=blockIdx.y, n0=blockIdx.x*128;
    {   // stage A
        const uint4* s0=(const uint4*)(g_Ah+b*6144);
        const uint4* s1=(const uint4*)(g_Al+b*6144);
        for(int e=tid;e<768;e+=512){
            int o=e/12, c=e%12;
            *(uint4*)(smu+LA_AH+o*104+c*8)=s0[e];
            *(uint4*)(smu+LA_AL+o*104+c*8)=s1[e];
        }
    }
    for(int e=tid;e<1024;e+=512){   // BT h part (k 0..63)
        int n=e>>3, blk=e&7;
        size_t src=((size_t)b*NPTS+n0+n)*64+blk*8;
        *(uint4*)(smu+LA_BTH+n*104+blk*8)=*(const uint4*)(shi+src);
        *(uint4*)(smu+LA_BTL+n*104+blk*8)=*(const uint4*)(slo+src);
    }
    for(int e=tid;e<512;e+=512){    // BT basis part (k 64..95)
        int n=e>>2, blk=e&3;
        *(uint4*)(smu+LA_BTH+n*104+64+blk*8)=*(const uint4*)((const u16*)g_basTh+(size_t)(n0+n)*32+blk*8);
        *(uint4*)(smu+LA_BTL+n*104+64+blk*8)=*(const uint4*)((const u16*)g_basTl+(size_t)(n0+n)*32+blk*8);
    }
    __syncthreads();
    const int m0=(wid&3)*16, nb0=(wid>>2)*32;
    float acc[4][4];
#pragma unroll
    for(int x=0;x<4;x++) for(int c=0;c<4;c++) acc[x][c]=0.f;
    for(int ks=0;ks<6;ks++){
        int k0=ks*16;
        u32 ah[4], al[4];
        int rA=(m0+gid)*104+k0+tid4*2;
        ah[0]=*(const u32*)(smu+LA_AH+rA);   ah[1]=*(const u32*)(smu+LA_AH+rA+8*104);
        ah[2]=*(const u32*)(smu+LA_AH+rA+8); ah[3]=*(const u32*)(smu+LA_AH+rA+8*104+8);
        al[0]=*(const u32*)(smu+LA_AL+rA);   al[1]=*(const u32*)(smu+LA_AL+rA+8*104);
        al[2]=*(const u32*)(smu+LA_AL+rA+8); al[3]=*(const u32*)(smu+LA_AL+rA+8*104+8);
#pragma unroll
        for(int nt=0;nt<4;nt++){
            int rb=(nb0+nt*8+gid)*104+k0+tid4*2;
            u32 bh0=*(const u32*)(smu+LA_BTH+rb), bh1=*(const u32*)(smu+LA_BTH+rb+8);
            u32 bl0=*(const u32*)(smu+LA_BTL+rb), bl1=*(const u32*)(smu+LA_BTL+rb+8);
            mma_bf16(acc[nt],ah,bh0,bh1);
            mma_bf16(acc[nt],ah,bl0,bl1);
            mma_bf16(acc[nt],al,bh0,bh1);
        }
    }
    __syncthreads();   // reuse smem for bounce
    // epilogue: bias + GELU + split -> bounce [n][72 o-pad]
    const int o0=m0+gid, o1=o0+8;
    float bb0=__ldg(wb+o0), bb1=__ldg(wb+o1);
#pragma unroll
    for(int nt=0;nt<4;nt++){
        int n=nb0+nt*8+tid4*2;
        float v0=gelu_exact(acc[nt][0]+bb0), v1=gelu_exact(acc[nt][1]+bb0);
        float v2=gelu_exact(acc[nt][2]+bb1), v3=gelu_exact(acc[nt][3]+bb1);
        u16 h0,l0,h1,l1,h2,l2,h3,l3;
        split_bf(v0,h0,l0); split_bf(v1,h1,l1); split_bf(v2,h2,l2); split_bf(v3,h3,l3);
        smu[EP_BNH+n*72+o0]=h0; smu[EP_BNH+(n+1)*72+o0]=h1;
        smu[EP_BNH+n*72+o1]=h2; smu[EP_BNH+(n+1)*72+o1]=h3;
        smu[EP_BNL+n*72+o0]=l0; smu[EP_BNL+(n+1)*72+o0]=l1;
        smu[EP_BNL+n*72+o1]=l2; smu[EP_BNL+(n+1)*72+o1]=l3;
    }
    __syncthreads();
    for(int e=tid;e<1024;e+=512){   // coalesced global write [b][n][o]
        int n=e>>3, blk=e&7;
        size_t dst=((size_t)b*NPTS+n0+n)*64+blk*8;
        *(uint4*)(dhi+dst)=*(const uint4*)(smu+EP_BNH+n*72+blk*8);
        *(uint4*)(dlo+dst)=*(const uint4*)(smu+EP_BNL+n*72+blk*8);
    }
}

// ---- projection ----
__global__ void k_proj(const bf16* __restrict__ hhi, const bf16* __restrict__ hlo,
                       const float* __restrict__ qw, const float* __restrict__ qb,
                       float* __restrict__ out){
    int t=threadIdx.x;
    int r=blockIdx.x*32 + (t>>3);
    int l8=t&7;
    size_t base=(size_t)r*64 + l8*8;
    float acc=0.f;
    uint4 qh=*(const uint4*)(hhi+base); uint4 ql=*(const uint4*)(hlo+base);
    u16 eh[8],el[8]; *(uint4*)eh=qh; *(uint4*)el=ql;
#pragma unroll
    for(int j=0;j<8;j++)
        acc += (__bfloat162float(__ushort_as_bfloat16(eh[j]))+__bfloat162float(__ushort_as_bfloat16(el[j])))*__ldg(qw+l8*8+j);
    acc += __shfl_down_sync(0xFFFFFFFFu,acc,4);
    acc += __shfl_down_sync(0xFFFFFFFFu,acc,2);
    acc += __shfl_down_sync(0xFFFFFFFFu,acc,1);
    if(l8==0) out[r]=acc+__ldg(qb);
}

// ---- launch ----
extern "C" void kernel_launch(void* const* d_in, const int* in_sizes, int n_in,
                              void* d_out, int out_size){
    const float* x =(const float*)d_in[0];
    const float* pw=(const float*)d_in[1];
    const float* pb=(const float*)d_in[2];
    const float* wr=(const float*)d_in[3];
    const float* wi=(const float*)d_in[4];
    const float* ww=(const float*)d_in[5];
    const float* wb=(const float*)d_in[6];
    const float* qw=(const float*)d_in[7];
    const float* qb=(const float*)d_in[8];
    float* out=(float*)d_out;

    bf16 *h0h,*h0l,*h1h,*h1l;
    cudaGetSymbolAddress((void**)&h0h,g_h0hi); cudaGetSymbolAddress((void**)&h0l,g_h0lo);
    cudaGetSymbolAddress((void**)&h1h,g_h1hi); cudaGetSymbolAddress((void**)&h1l,g_h1lo);

    cudaFuncSetAttribute(k_fwd,  cudaFuncAttributeMaxDynamicSharedMemorySize, 87040);
    cudaFuncSetAttribute(k_layer,cudaFuncAttributeMaxDynamicSharedMemorySize, 79872);

    k_basis<<<1024,256>>>();
    k_lift<<<HSIZE/256,256>>>(x,pw,pb);

    const bf16 *shi=h0h,*slo=h0l; bf16 *dhi=h1h,*dlo=h1l;
    for(int l=0;l<4;l++){
        k_fwd<<<dim3(32,8),128,87040>>>(shi,slo);
        k_fred<<<512,256>>>();
        k_mix<<<64,256>>>(wr+l*65536, wi+l*65536);
        k_prepA<<<64,128>>>(ww+l*4096);
        k_layer<<<dim3(64,64),512,79872>>>(shi,slo,dhi,dlo,wb+l*64);
        const bf16* th=shi; const bf16* tl=slo;
        shi=dhi; slo=dlo; dhi=(bf16*)th; dlo=(bf16*)tl;
    }
    k_proj<<<16384,256>>>(shi,slo,qw,qb,out);
}

// round 12
// speedup vs baseline: 1.2156x; 1.0337x over previous
#include <cuda_runtime.h>
#include <cuda_bf16.h>
#include <cstdint>

#define NPTS 8192
#define HSIZE (64*NPTS*64)      // [b][n][i] elems = 33.5M
typedef unsigned int u32; typedef unsigned short u16; typedef __nv_bfloat16 bf16;

// ---- device scratch ----
__device__ bf16 g_h0hi[HSIZE], g_h0lo[HSIZE], g_h1hi[HSIZE], g_h1lo[HSIZE];
__device__ bf16 g_bash[32*NPTS], g_basl[32*NPTS];    // [freq r][pos]  r<16 cos, r>=16 sin
__device__ bf16 g_basTh[NPTS*32], g_basTl[NPTS*32];  // [pos][r]
__device__ float g_Fp[8*4096*32];
__device__ u16 g_Ah[64*64*96], g_Al[64*64*96];       // per-batch A [o][96]

__device__ __forceinline__ float gelu_exact(float v){ return 0.5f*v*(1.0f+erff(v*0.7071067811865476f)); }
__device__ __forceinline__ void split_bf(float v, u16& h, u16& l){
    bf16 bh=__float2bfloat16(v); bf16 bl=__float2bfloat16(v-__bfloat162float(bh));
    h=__bfloat16_as_ushort(bh); l=__bfloat16_as_ushort(bl);
}
__device__ __forceinline__ void mma_bf16(float* d, const u32* a, u32 b0, u32 b1){
    asm volatile("mma.sync.aligned.m16n8k16.row.col.f32.bf16.bf16.f32 "
        "{%0,%1,%2,%3}, {%4,%5,%6,%7}, {%8,%9}, {%0,%1,%2,%3};"
        : "+f"(d[0]),"+f"(d[1]),"+f"(d[2]),"+f"(d[3])
        : "r"(a[0]),"r"(a[1]),"r"(a[2]),"r"(a[3]),"r"(b0),"r"(b1));
}

// ---- init: basis tables (blocks 0..1023) + lifting (blocks 1024..) ----
__global__ void k_init(const float* __restrict__ x, const float* __restrict__ pw,
                       const float* __restrict__ pb){
    if(blockIdx.x < 1024){
        int idx=blockIdx.x*256+threadIdx.x;          // < 32*8192
        int r=idx>>13, n=idx&(NPTS-1), k=r&15;
        int rm=(k*n)&(NPTS-1);
        float a=(float)rm*(1.f/4096.f); float s,c; sincospif(a,&s,&c);
        float v=(r<16)?c:s;
        u16 hb,lb; split_bf(v,hb,lb);
        g_bash[r*NPTS+n]=__ushort_as_bfloat16(hb);  g_basl[r*NPTS+n]=__ushort_as_bfloat16(lb);
        g_basTh[n*32+r]=__ushort_as_bfloat16(hb);   g_basTl[n*32+r]=__ushort_as_bfloat16(lb);
    } else {
        int idx=(blockIdx.x-1024)*256+threadIdx.x;   // < HSIZE
        int b=idx>>19, n=(idx>>6)&(NPTS-1), i=idx&63;
        float v = x[(b<<13)|n]*pw[2*i] + ((float)n*(1.f/8191.f))*pw[2*i+1] + pb[i];
        u16 hb,lb; split_bf(v,hb,lb);
        g_h0hi[idx]=__ushort_as_bfloat16(hb); g_h0lo[idx]=__ushort_as_bfloat16(lb);
    }
}

// ---- forward DFT (once per layer): rows=(b,i) 128/CTA, N=32, K split 8x1024 ----
#define FW_A2H 0
#define FW_A2L 17408
#define FW_BH  34816
#define FW_BL  39168
__global__ void __launch_bounds__(128) k_fwd(const bf16* __restrict__ hhi, const bf16* __restrict__ hlo){
    extern __shared__ u16 smu[];
    const int tid=threadIdx.x, lane=tid&31, wid=tid>>5;
    const int gid=lane>>2, tid4=lane&3;
    const int mb=blockIdx.x, split=blockIdx.y;
    float acc[2][4][4];
#pragma unroll
    for(int a=0;a<2;a++) for(int b=0;b<4;b++) for(int c=0;c<4;c++) acc[a][b][c]=0.f;
    for(int ch=0;ch<8;ch++){
        int nwin=split*1024+ch*128;
        for(int it=0;it<4;it++){
            int pp=it*16+(tid>>3), iblk=tid&7;
#pragma unroll
            for(int bl=0;bl<2;bl++){
                size_t base=((size_t)(mb*2+bl)*NPTS + nwin + pp*2)*64 + iblk*8;
                uint4 q0=*(const uint4*)(hhi+base); uint4 q1=*(const uint4*)(hhi+base+64);
                u16 e0[8],e1[8]; *(uint4*)e0=q0; *(uint4*)e1=q1;
                u32* dst=(u32*)(smu+FW_A2H)+pp*136+bl*64+iblk*8;
#pragma unroll
                for(int j=0;j<8;j++) dst[j]=(u32)e0[j]|((u32)e1[j]<<16);
                q0=*(const uint4*)(hlo+base); q1=*(const uint4*)(hlo+base+64);
                *(uint4*)e0=q0; *(uint4*)e1=q1;
                dst=(u32*)(smu+FW_A2L)+pp*136+bl*64+iblk*8;
#pragma unroll
                for(int j=0;j<8;j++) dst[j]=(u32)e0[j]|((u32)e1[j]<<16);
            }
        }
        for(int e=tid;e<512;e+=128){
            int f=e>>4, blk=e&15;
            *(uint4*)(smu+FW_BH+f*136+blk*8)=*(const uint4*)((const u16*)g_bash+f*NPTS+nwin+blk*8);
            *(uint4*)(smu+FW_BL+f*136+blk*8)=*(const uint4*)((const u16*)g_basl+f*NPTS+nwin+blk*8);
        }
        __syncthreads();
        const int m0=wid*32;
        const u32* A2h=(const u32*)(smu+FW_A2H);
        const u32* A2l=(const u32*)(smu+FW_A2L);
        for(int ks=0;ks<8;ks++){
            int k0=ks*16, p=k0/2+tid4;
            u32 ah[2][4], al[2][4];
#pragma unroll
            for(int mt=0;mt<2;mt++){
                int m=m0+mt*16+gid;
                ah[mt][0]=A2h[p*136+m];     ah[mt][1]=A2h[p*136+m+8];
                ah[mt][2]=A2h[(p+4)*136+m]; ah[mt][3]=A2h[(p+4)*136+m+8];
                al[mt][0]=A2l[p*136+m];     al[mt][1]=A2l[p*136+m+8];
                al[mt][2]=A2l[(p+4)*136+m]; al[mt][3]=A2l[(p+4)*136+m+8];
            }
#pragma unroll
            for(int nt=0;nt<4;nt++){
                int rb=(nt*8+gid)*136+k0+tid4*2;
                u32 bh0=*(const u32*)(smu+FW_BH+rb), bh1=*(const u32*)(smu+FW_BH+rb+8);
                u32 bl0=*(const u32*)(smu+FW_BL+rb), bl1=*(const u32*)(smu+FW_BL+rb+8);
#pragma unroll
                for(int mt=0;mt<2;mt++){
                    mma_bf16(acc[mt][nt],ah[mt],bh0,bh1);
                    mma_bf16(acc[mt][nt],ah[mt],bl0,bl1);
                    mma_bf16(acc[mt][nt],al[mt],bh0,bh1);
                }
            }
        }
        __syncthreads();
    }
#pragma unroll
    for(int mt=0;mt<2;mt++)
#pragma unroll
    for(int nt=0;nt<4;nt++){
        int row=mb*128+wid*32+mt*16+gid, col=nt*8+tid4*2;
        float* dp=g_Fp+(size_t)split*131072+row*32+col;
        *(float2*)dp=make_float2(acc[mt][nt][0],acc[mt][nt][1]);
        *(float2*)(dp+8*32)=make_float2(acc[mt][nt][2],acc[mt][nt][3]);
    }
}

// ---- merged: reduce F partials + mode mix + build A  (CTA = batch) ----
__global__ void __launch_bounds__(256) k_mixA(const float* __restrict__ wr, const float* __restrict__ wi,
                                              const float* __restrict__ ww){
    __shared__ float Fs[64][32];
    __shared__ float Gs[2][16][64];
    const int b=blockIdx.x, tid=threadIdx.x;
#pragma unroll
    for(int t=0;t<8;t++){
        int e=tid+t*256;
        float s=0.f;
#pragma unroll
        for(int p=0;p<8;p++) s+=g_Fp[p*131072 + b*2048 + e];
        Fs[e>>5][e&31]=s;
    }
    __syncthreads();
    const int k=tid&15, og=tid>>4;
#pragma unroll
    for(int rep=0;rep<4;rep++){
        int o=og+rep*16;
        float gre=0.f,gim=0.f;
#pragma unroll 8
        for(int i=0;i<64;i++){
            float fr=Fs[i][k], S=Fs[i][16+k];
            float wrv=wr[(i*64+o)*16+k], wiv=wi[(i*64+o)*16+k];
            gre+=fr*wrv+S*wiv; gim+=fr*wiv-S*wrv;
        }
        float sc=(k==0?1.0f:2.0f)*(1.0f/(float)NPTS);
        Gs[0][k][o]=gre*sc;
        Gs[1][k][o]=gim*sc;
    }
    __syncthreads();
    for(int t=tid;t<6144;t+=256){
        int o=t/96, c=t%96;
        float v;
        if(c<64) v=ww[o*64+c];
        else if(c<80) v= Gs[0][c-64][o];
        else          v=-Gs[1][c-80][o];
        u16 hb,lb; split_bf(v,hb,lb);
        g_Ah[b*6144+t]=hb; g_Al[b*6144+t]=lb;
    }
}

// ---- lean layer, 512 threads: D[64 o][128 n] = A[64x96]·BT; bias+GELU+split+store ----
#define LA_AH 0
#define LA_AL 6656
#define LA_BTH 13312
#define LA_BTL 26624
#define EP_BNH 0
#define EP_BNL 9216
__global__ void __launch_bounds__(512,2) k_layer(const bf16* __restrict__ shi, const bf16* __restrict__ slo,
                                                 bf16* __restrict__ dhi, bf16* __restrict__ dlo,
                                                 const float* __restrict__ wb){
    extern __shared__ __align__(16) u16 smu[];
    const int tid=threadIdx.x, lane=tid&31, wid=tid>>5;
    const int gid=lane>>2, tid4=lane&3;
    const int b=blockIdx.y, n0=blockIdx.x*128;
    {   // stage A
        const uint4* s0=(const uint4*)(g_Ah+b*6144);
        const uint4* s1=(const uint4*)(g_Al+b*6144);
        for(int e=tid;e<768;e+=512){
            int o=e/12, c=e%12;
            *(uint4*)(smu+LA_AH+o*104+c*8)=s0[e];
            *(uint4*)(smu+LA_AL+o*104+c*8)=s1[e];
        }
    }
    for(int e=tid;e<1024;e+=512){   // BT h part (k 0..63)
        int n=e>>3, blk=e&7;
        size_t src=((size_t)b*NPTS+n0+n)*64+blk*8;
        *(uint4*)(smu+LA_BTH+n*104+blk*8)=*(const uint4*)(shi+src);
        *(uint4*)(smu+LA_BTL+n*104+blk*8)=*(const uint4*)(slo+src);
    }
    for(int e=tid;e<512;e+=512){    // BT basis part (k 64..95)
        int n=e>>2, blk=e&3;
        *(uint4*)(smu+LA_BTH+n*104+64+blk*8)=*(const uint4*)((const u16*)g_basTh+(size_t)(n0+n)*32+blk*8);
        *(uint4*)(smu+LA_BTL+n*104+64+blk*8)=*(const uint4*)((const u16*)g_basTl+(size_t)(n0+n)*32+blk*8);
    }
    __syncthreads();
    const int m0=(wid&3)*16, nb0=(wid>>2)*32;
    float acc[4][4];
#pragma unroll
    for(int x=0;x<4;x++) for(int c=0;c<4;c++) acc[x][c]=0.f;
    for(int ks=0;ks<6;ks++){
        int k0=ks*16;
        u32 ah[4], al[4];
        int rA=(m0+gid)*104+k0+tid4*2;
        ah[0]=*(const u32*)(smu+LA_AH+rA);   ah[1]=*(const u32*)(smu+LA_AH+rA+8*104);
        ah[2]=*(const u32*)(smu+LA_AH+rA+8); ah[3]=*(const u32*)(smu+LA_AH+rA+8*104+8);
        al[0]=*(const u32*)(smu+LA_AL+rA);   al[1]=*(const u32*)(smu+LA_AL+rA+8*104);
        al[2]=*(const u32*)(smu+LA_AL+rA+8); al[3]=*(const u32*)(smu+LA_AL+rA+8*104+8);
#pragma unroll
        for(int nt=0;nt<4;nt++){
            int rb=(nb0+nt*8+gid)*104+k0+tid4*2;
            u32 bh0=*(const u32*)(smu+LA_BTH+rb), bh1=*(const u32*)(smu+LA_BTH+rb+8);
            u32 bl0=*(const u32*)(smu+LA_BTL+rb), bl1=*(const u32*)(smu+LA_BTL+rb+8);
            mma_bf16(acc[nt],ah,bh0,bh1);
            mma_bf16(acc[nt],ah,bl0,bl1);
            mma_bf16(acc[nt],al,bh0,bh1);
        }
    }
    __syncthreads();   // reuse smem for bounce
    const int o0=m0+gid, o1=o0+8;
    float bb0=__ldg(wb+o0), bb1=__ldg(wb+o1);
#pragma unroll
    for(int nt=0;nt<4;nt++){
        int n=nb0+nt*8+tid4*2;
        float v0=gelu_exact(acc[nt][0]+bb0), v1=gelu_exact(acc[nt][1]+bb0);
        float v2=gelu_exact(acc[nt][2]+bb1), v3=gelu_exact(acc[nt][3]+bb1);
        u16 h0,l0,h1,l1,h2,l2,h3,l3;
        split_bf(v0,h0,l0); split_bf(v1,h1,l1); split_bf(v2,h2,l2); split_bf(v3,h3,l3);
        smu[EP_BNH+n*72+o0]=h0; smu[EP_BNH+(n+1)*72+o0]=h1;
        smu[EP_BNH+n*72+o1]=h2; smu[EP_BNH+(n+1)*72+o1]=h3;
        smu[EP_BNL+n*72+o0]=l0; smu[EP_BNL+(n+1)*72+o0]=l1;
        smu[EP_BNL+n*72+o1]=l2; smu[EP_BNL+(n+1)*72+o1]=l3;
    }
    __syncthreads();
    for(int e=tid;e<1024;e+=512){   // coalesced global write [b][n][o]
        int n=e>>3, blk=e&7;
        size_t dst=((size_t)b*NPTS+n0+n)*64+blk*8;
        *(uint4*)(dhi+dst)=*(const uint4*)(smu+EP_BNH+n*72+blk*8);
        *(uint4*)(dlo+dst)=*(const uint4*)(smu+EP_BNL+n*72+blk*8);
    }
}

// ---- projection ----
__global__ void k_proj(const bf16* __restrict__ hhi, const bf16* __restrict__ hlo,
                       const float* __restrict__ qw, const float* __restrict__ qb,
                       float* __restrict__ out){
    int t=threadIdx.x;
    int r=blockIdx.x*32 + (t>>3);
    int l8=t&7;
    size_t base=(size_t)r*64 + l8*8;
    float acc=0.f;
    uint4 qh=*(const uint4*)(hhi+base); uint4 ql=*(const uint4*)(hlo+base);
    u16 eh[8],el[8]; *(uint4*)eh=qh; *(uint4*)el=ql;
#pragma unroll
    for(int j=0;j<8;j++)
        acc += (__bfloat162float(__ushort_as_bfloat16(eh[j]))+__bfloat162float(__ushort_as_bfloat16(el[j])))*__ldg(qw+l8*8+j);
    acc += __shfl_down_sync(0xFFFFFFFFu,acc,4);
    acc += __shfl_down_sync(0xFFFFFFFFu,acc,2);
    acc += __shfl_down_sync(0xFFFFFFFFu,acc,1);
    if(l8==0) out[r]=acc+__ldg(qb);
}

// ---- launch ----
extern "C" void kernel_launch(void* const* d_in, const int* in_sizes, int n_in,
                              void* d_out, int out_size){
    const float* x =(const float*)d_in[0];
    const float* pw=(const float*)d_in[1];
    const float* pb=(const float*)d_in[2];
    const float* wr=(const float*)d_in[3];
    const float* wi=(const float*)d_in[4];
    const float* ww=(const float*)d_in[5];
    const float* wb=(const float*)d_in[6];
    const float* qw=(const float*)d_in[7];
    const float* qb=(const float*)d_in[8];
    float* out=(float*)d_out;

    bf16 *h0h,*h0l,*h1h,*h1l;
    cudaGetSymbolAddress((void**)&h0h,g_h0hi); cudaGetSymbolAddress((void**)&h0l,g_h0lo);
    cudaGetSymbolAddress((void**)&h1h,g_h1hi); cudaGetSymbolAddress((void**)&h1l,g_h1lo);

    cudaFuncSetAttribute(k_fwd,  cudaFuncAttributeMaxDynamicSharedMemorySize, 87040);
    cudaFuncSetAttribute(k_layer,cudaFuncAttributeMaxDynamicSharedMemorySize, 79872);

    k_init<<<1024 + HSIZE/256, 256>>>(x,pw,pb);

    const bf16 *shi=h0h,*slo=h0l; bf16 *dhi=h1h,*dlo=h1l;
    for(int l=0;l<4;l++){
        k_fwd<<<dim3(32,8),128,87040>>>(shi,slo);
        k_mixA<<<64,256>>>(wr+l*65536, wi+l*65536, ww+l*4096);
        k_layer<<<dim3(64,64),512,79872>>>(shi,slo,dhi,dlo,wb+l*64);
        const bf16* th=shi; const bf16* tl=slo;
        shi=dhi; slo=dlo; dhi=(bf16*)th; dlo=(bf16*)tl;
    }
    k_proj<<<16384,256>>>(shi,slo,qw,qb,out);
}

// round 14
// speedup vs baseline: 1.2485x; 1.0271x over previous
#include <cuda_runtime.h>
#include <cuda_bf16.h>
#include <cstdint>

#define NPTS 8192
#define HSIZE (64*NPTS*64)      // [b][n][i] elems = 33.5M
typedef unsigned int u32; typedef unsigned short u16; typedef __nv_bfloat16 bf16;

// ---- device scratch ----
__device__ bf16 g_h0hi[HSIZE], g_h0lo[HSIZE], g_h1hi[HSIZE], g_h1lo[HSIZE];
__device__ bf16 g_bash[32*NPTS], g_basl[32*NPTS];    // [freq r][pos]  r<16 cos, r>=16 sin
__device__ bf16 g_basTh[NPTS*32], g_basTl[NPTS*32];  // [pos][r]
__device__ float g_Fp[8*4096*32];
__device__ u16 g_Ah[64*64*96], g_Al[64*64*96];       // per-batch A [o][96]

__device__ __forceinline__ float gelu_exact(float v){ return 0.5f*v*(1.0f+erff(v*0.7071067811865476f)); }
__device__ __forceinline__ void split_bf(float v, u16& h, u16& l){
    bf16 bh=__float2bfloat16(v); bf16 bl=__float2bfloat16(v-__bfloat162float(bh));
    h=__bfloat16_as_ushort(bh); l=__bfloat16_as_ushort(bl);
}
__device__ __forceinline__ void mma_bf16(float* d, const u32* a, u32 b0, u32 b1){
    asm volatile("mma.sync.aligned.m16n8k16.row.col.f32.bf16.bf16.f32 "
        "{%0,%1,%2,%3}, {%4,%5,%6,%7}, {%8,%9}, {%0,%1,%2,%3};"
        : "+f"(d[0]),"+f"(d[1]),"+f"(d[2]),"+f"(d[3])
        : "r"(a[0]),"r"(a[1]),"r"(a[2]),"r"(a[3]),"r"(b0),"r"(b1));
}
__device__ __forceinline__ u32 sptr(const void* p){ return (u32)__cvta_generic_to_shared(p); }
__device__ __forceinline__ void ldsm4(u32* r, u32 a){
    asm volatile("ldmatrix.sync.aligned.m8n8.x4.shared.b16 {%0,%1,%2,%3}, [%4];"
        : "=r"(r[0]),"=r"(r[1]),"=r"(r[2]),"=r"(r[3]) : "r"(a));
}

// ---- init: basis tables (blocks 0..1023) + lifting (blocks 1024..) ----
__global__ void k_init(const float* __restrict__ x, const float* __restrict__ pw,
                       const float* __restrict__ pb){
    if(blockIdx.x < 1024){
        int idx=blockIdx.x*256+threadIdx.x;          // < 32*8192
        int r=idx>>13, n=idx&(NPTS-1), k=r&15;
        int rm=(k*n)&(NPTS-1);
        float a=(float)rm*(1.f/4096.f); float s,c; sincospif(a,&s,&c);
        float v=(r<16)?c:s;
        u16 hb,lb; split_bf(v,hb,lb);
        g_bash[r*NPTS+n]=__ushort_as_bfloat16(hb);  g_basl[r*NPTS+n]=__ushort_as_bfloat16(lb);
        g_basTh[n*32+r]=__ushort_as_bfloat16(hb);   g_basTl[n*32+r]=__ushort_as_bfloat16(lb);
    } else {
        int idx=(blockIdx.x-1024)*256+threadIdx.x;   // < HSIZE
        int b=idx>>19, n=(idx>>6)&(NPTS-1), i=idx&63;
        float v = x[(b<<13)|n]*pw[2*i] + ((float)n*(1.f/8191.f))*pw[2*i+1] + pb[i];
        u16 hb,lb; split_bf(v,hb,lb);
        g_h0hi[idx]=__ushort_as_bfloat16(hb); g_h0lo[idx]=__ushort_as_bfloat16(lb);
    }
}

// ---- forward DFT (once per layer): rows=(b,i) 128/CTA, N=32, K split 8x1024 ----
// (R12-proven version: u32 pair-pack transpose + scalar fragment loads)
#define FW_A2H 0
#define FW_A2L 17408
#define FW_BH  34816
#define FW_BL  39168
__global__ void __launch_bounds__(128) k_fwd(const bf16* __restrict__ hhi, const bf16* __restrict__ hlo){
    extern __shared__ u16 smu[];
    const int tid=threadIdx.x, lane=tid&31, wid=tid>>5;
    const int gid=lane>>2, tid4=lane&3;
    const int mb=blockIdx.x, split=blockIdx.y;
    float acc[2][4][4];
#pragma unroll
    for(int a=0;a<2;a++) for(int b=0;b<4;b++) for(int c=0;c<4;c++) acc[a][b][c]=0.f;
    for(int ch=0;ch<8;ch++){
        int nwin=split*1024+ch*128;
        for(int it=0;it<4;it++){
            int pp=it*16+(tid>>3), iblk=tid&7;
#pragma unroll
            for(int bl=0;bl<2;bl++){
                size_t base=((size_t)(mb*2+bl)*NPTS + nwin + pp*2)*64 + iblk*8;
                uint4 q0=*(const uint4*)(hhi+base); uint4 q1=*(const uint4*)(hhi+base+64);
                u16 e0[8],e1[8]; *(uint4*)e0=q0; *(uint4*)e1=q1;
                u32* dst=(u32*)(smu+FW_A2H)+pp*136+bl*64+iblk*8;
#pragma unroll
                for(int j=0;j<8;j++) dst[j]=(u32)e0[j]|((u32)e1[j]<<16);
                q0=*(const uint4*)(hlo+base); q1=*(const uint4*)(hlo+base+64);
                *(uint4*)e0=q0; *(uint4*)e1=q1;
                dst=(u32*)(smu+FW_A2L)+pp*136+bl*64+iblk*8;
#pragma unroll
                for(int j=0;j<8;j++) dst[j]=(u32)e0[j]|((u32)e1[j]<<16);
            }
        }
        for(int e=tid;e<512;e+=128){
            int f=e>>4, blk=e&15;
            *(uint4*)(smu+FW_BH+f*136+blk*8)=*(const uint4*)((const u16*)g_bash+f*NPTS+nwin+blk*8);
            *(uint4*)(smu+FW_BL+f*136+blk*8)=*(const uint4*)((const u16*)g_basl+f*NPTS+nwin+blk*8);
        }
        __syncthreads();
        const int m0=wid*32;
        const u32* A2h=(const u32*)(smu+FW_A2H);
        const u32* A2l=(const u32*)(smu+FW_A2L);
        for(int ks=0;ks<8;ks++){
            int k0=ks*16, p=k0/2+tid4;
            u32 ah[2][4], al[2][4];
#pragma unroll
            for(int mt=0;mt<2;mt++){
                int m=m0+mt*16+gid;
                ah[mt][0]=A2h[p*136+m];     ah[mt][1]=A2h[p*136+m+8];
                ah[mt][2]=A2h[(p+4)*136+m]; ah[mt][3]=A2h[(p+4)*136+m+8];
                al[mt][0]=A2l[p*136+m];     al[mt][1]=A2l[p*136+m+8];
                al[mt][2]=A2l[(p+4)*136+m]; al[mt][3]=A2l[(p+4)*136+m+8];
            }
#pragma unroll
            for(int nt=0;nt<4;nt++){
                int rb=(nt*8+gid)*136+k0+tid4*2;
                u32 bh0=*(const u32*)(smu+FW_BH+rb), bh1=*(const u32*)(smu+FW_BH+rb+8);
                u32 bl0=*(const u32*)(smu+FW_BL+rb), bl1=*(const u32*)(smu+FW_BL+rb+8);
#pragma unroll
                for(int mt=0;mt<2;mt++){
                    mma_bf16(acc[mt][nt],ah[mt],bh0,bh1);
                    mma_bf16(acc[mt][nt],ah[mt],bl0,bl1);
                    mma_bf16(acc[mt][nt],al[mt],bh0,bh1);
                }
            }
        }
        __syncthreads();
    }
#pragma unroll
    for(int mt=0;mt<2;mt++)
#pragma unroll
    for(int nt=0;nt<4;nt++){
        int row=mb*128+wid*32+mt*16+gid, col=nt*8+tid4*2;
        float* dp=g_Fp+(size_t)split*131072+row*32+col;
        *(float2*)dp=make_float2(acc[mt][nt][0],acc[mt][nt][1]);
        *(float2*)(dp+8*32)=make_float2(acc[mt][nt][2],acc[mt][nt][3]);
    }
}

// ---- merged: reduce F partials + mode mix + build A  (CTA = batch) ----
__global__ void __launch_bounds__(256) k_mixA(const float* __restrict__ wr, const float* __restrict__ wi,
                                              const float* __restrict__ ww){
    __shared__ float Fs[64][32];
    __shared__ float Gs[2][16][64];
    const int b=blockIdx.x, tid=threadIdx.x;
#pragma unroll
    for(int t=0;t<8;t++){
        int e=tid+t*256;
        float s=0.f;
#pragma unroll
        for(int p=0;p<8;p++) s+=g_Fp[p*131072 + b*2048 + e];
        Fs[e>>5][e&31]=s;
    }
    __syncthreads();
    const int k=tid&15, og=tid>>4;
#pragma unroll
    for(int rep=0;rep<4;rep++){
        int o=og+rep*16;
        float gre=0.f,gim=0.f;
#pragma unroll 8
        for(int i=0;i<64;i++){
            float fr=Fs[i][k], S=Fs[i][16+k];
            float wrv=wr[(i*64+o)*16+k], wiv=wi[(i*64+o)*16+k];
            gre+=fr*wrv+S*wiv; gim+=fr*wiv-S*wrv;
        }
        float sc=(k==0?1.0f:2.0f)*(1.0f/(float)NPTS);
        Gs[0][k][o]=gre*sc;
        Gs[1][k][o]=gim*sc;
    }
    __syncthreads();
    for(int t=tid;t<6144;t+=256){
        int o=t/96, c=t%96;
        float v;
        if(c<64) v=ww[o*64+c];
        else if(c<80) v= Gs[0][c-64][o];
        else          v=-Gs[1][c-80][o];
        u16 hb,lb; split_bf(v,hb,lb);
        g_Ah[b*6144+t]=hb; g_Al[b*6144+t]=lb;
    }
}

// ---- lean layer, 512 threads: ONLY change vs R12 = ldmatrix fragment loads ----
#define LA_AH 0
#define LA_AL 6656
#define LA_BTH 13312
#define LA_BTL 26624
#define EP_BNH 0
#define EP_BNL 9216
__global__ void __launch_bounds__(512,2) k_layer(const bf16* __restrict__ shi, const bf16* __restrict__ slo,
                                                 bf16* __restrict__ dhi, bf16* __restrict__ dlo,
                                                 const float* __restrict__ wb){
    extern __shared__ __align__(16) u16 smu[];
    const int tid=threadIdx.x, lane=tid&31, wid=tid>>5;
    const int gid=lane>>2, tid4=lane&3;
    const int b=blockIdx.y, n0=blockIdx.x*128;
    {   // stage A
        const uint4* s0=(const uint4*)(g_Ah+b*6144);
        const uint4* s1=(const uint4*)(g_Al+b*6144);
        for(int e=tid;e<768;e+=512){
            int o=e/12, c=e%12;
            *(uint4*)(smu+LA_AH+o*104+c*8)=s0[e];
            *(uint4*)(smu+LA_AL+o*104+c*8)=s1[e];
        }
    }
    for(int e=tid;e<1024;e+=512){   // BT h part (k 0..63)
        int n=e>>3, blk=e&7;
        size_t src=((size_t)b*NPTS+n0+n)*64+blk*8;
        *(uint4*)(smu+LA_BTH+n*104+blk*8)=*(const uint4*)(shi+src);
        *(uint4*)(smu+LA_BTL+n*104+blk*8)=*(const uint4*)(slo+src);
    }
    {   int e=tid;                  // BT basis part (k 64..95): 512 uint4
        int n=e>>2, blk=e&3;
        *(uint4*)(smu+LA_BTH+n*104+64+blk*8)=*(const uint4*)((const u16*)g_basTh+(size_t)(n0+n)*32+blk*8);
        *(uint4*)(smu+LA_BTL+n*104+64+blk*8)=*(const uint4*)((const u16*)g_basTl+(size_t)(n0+n)*32+blk*8);
    }
    __syncthreads();
    const int m0=(wid&3)*16, nb0=(wid>>2)*32;
    float acc[4][4];
#pragma unroll
    for(int x=0;x<4;x++) for(int c=0;c<4;c++) acc[x][c]=0.f;
    const u32 S=sptr(smu);
    // A fragment addresses: lanes 0-15 -> rows m0..m0+15 (k-lo), lanes 16-31 -> same rows (k-hi)
    u32 aA =S+2u*(LA_AH + (m0+(lane&15))*104 + ((lane>>4)<<3));
    u32 aAl=S+2u*(LA_AL + (m0+(lane&15))*104 + ((lane>>4)<<3));
    {
        int brow=nb0+((lane>>4)<<3)+(lane&7), bcol=(lane&8);
        u32 aB0h=S+2u*(LA_BTH+brow*104+bcol), aB1h=aB0h+2u*16*104;
        u32 aB0l=S+2u*(LA_BTL+brow*104+bcol), aB1l=aB0l+2u*16*104;
#pragma unroll
        for(int ks=0;ks<6;ks++){
            u32 ah[4],al[4],bh0[4],bh1[4],bl0[4],bl1[4];
            ldsm4(ah,aA); ldsm4(al,aAl);
            ldsm4(bh0,aB0h); ldsm4(bh1,aB1h);
            ldsm4(bl0,aB0l); ldsm4(bl1,aB1l);
            mma_bf16(acc[0],ah,bh0[0],bh0[1]); mma_bf16(acc[0],ah,bl0[0],bl0[1]); mma_bf16(acc[0],al,bh0[0],bh0[1]);
            mma_bf16(acc[1],ah,bh0[2],bh0[3]); mma_bf16(acc[1],ah,bl0[2],bl0[3]); mma_bf16(acc[1],al,bh0[2],bh0[3]);
            mma_bf16(acc[2],ah,bh1[0],bh1[1]); mma_bf16(acc[2],ah,bl1[0],bl1[1]); mma_bf16(acc[2],al,bh1[0],bh1[1]);
            mma_bf16(acc[3],ah,bh1[2],bh1[3]); mma_bf16(acc[3],ah,bl1[2],bl1[3]); mma_bf16(acc[3],al,bh1[2],bh1[3]);
            aA+=32; aAl+=32; aB0h+=32; aB1h+=32; aB0l+=32; aB1l+=32;
        }
    }
    __syncthreads();   // reuse smem for bounce
    const int o0=m0+gid, o1=o0+8;
    float bb0=__ldg(wb+o0), bb1=__ldg(wb+o1);
#pragma unroll
    for(int nt=0;nt<4;nt++){
        int n=nb0+nt*8+tid4*2;
        float v0=gelu_exact(acc[nt][0]+bb0), v1=gelu_exact(acc[nt][1]+bb0);
        float v2=gelu_exact(acc[nt][2]+bb1), v3=gelu_exact(acc[nt][3]+bb1);
        u16 h0,l0,h1,l1,h2,l2,h3,l3;
        split_bf(v0,h0,l0); split_bf(v1,h1,l1); split_bf(v2,h2,l2); split_bf(v3,h3,l3);
        smu[EP_BNH+n*72+o0]=h0; smu[EP_BNH+(n+1)*72+o0]=h1;
        smu[EP_BNH+n*72+o1]=h2; smu[EP_BNH+(n+1)*72+o1]=h3;
        smu[EP_BNL+n*72+o0]=l0; smu[EP_BNL+(n+1)*72+o0]=l1;
        smu[EP_BNL+n*72+o1]=l2; smu[EP_BNL+(n+1)*72+o1]=l3;
    }
    __syncthreads();
    for(int e=tid;e<1024;e+=512){   // coalesced global write [b][n][o]
        int n=e>>3, blk=e&7;
        size_t dst=((size_t)b*NPTS+n0+n)*64+blk*8;
        *(uint4*)(dhi+dst)=*(const uint4*)(smu+EP_BNH+n*72+blk*8);
        *(uint4*)(dlo+dst)=*(const uint4*)(smu+EP_BNL+n*72+blk*8);
    }
}

// ---- projection ----
__global__ void k_proj(const bf16* __restrict__ hhi, const bf16* __restrict__ hlo,
                       const float* __restrict__ qw, const float* __restrict__ qb,
                       float* __restrict__ out){
    int t=threadIdx.x;
    int r=blockIdx.x*32 + (t>>3);
    int l8=t&7;
    size_t base=(size_t)r*64 + l8*8;
    float acc=0.f;
    uint4 qh=*(const uint4*)(hhi+base); uint4 ql=*(const uint4*)(hlo+base);
    u16 eh[8],el[8]; *(uint4*)eh=qh; *(uint4*)el=ql;
#pragma unroll
    for(int j=0;j<8;j++)
        acc += (__bfloat162float(__ushort_as_bfloat16(eh[j]))+__bfloat162float(__ushort_as_bfloat16(el[j])))*__ldg(qw+l8*8+j);
    acc += __shfl_down_sync(0xFFFFFFFFu,acc,4);
    acc += __shfl_down_sync(0xFFFFFFFFu,acc,2);
    acc += __shfl_down_sync(0xFFFFFFFFu,acc,1);
    if(l8==0) out[r]=acc+__ldg(qb);
}

// ---- launch ----
extern "C" void kernel_launch(void* const* d_in, const int* in_sizes, int n_in,
                              void* d_out, int out_size){
    const float* x =(const float*)d_in[0];
    const float* pw=(const float*)d_in[1];
    const float* pb=(const float*)d_in[2];
    const float* wr=(const float*)d_in[3];
    const float* wi=(const float*)d_in[4];
    const float* ww=(const float*)d_in[5];
    const float* wb=(const float*)d_in[6];
    const float* qw=(const float*)d_in[7];
    const float* qb=(const float*)d_in[8];
    float* out=(float*)d_out;

    bf16 *h0h,*h0l,*h1h,*h1l;
    cudaGetSymbolAddress((void**)&h0h,g_h0hi); cudaGetSymbolAddress((void**)&h0l,g_h0lo);
    cudaGetSymbolAddress((void**)&h1h,g_h1hi); cudaGetSymbolAddress((void**)&h1l,g_h1lo);

    cudaFuncSetAttribute(k_fwd,  cudaFuncAttributeMaxDynamicSharedMemorySize, 87040);
    cudaFuncSetAttribute(k_layer,cudaFuncAttributeMaxDynamicSharedMemorySize, 79872);

    k_init<<<1024 + HSIZE/256, 256>>>(x,pw,pb);

    const bf16 *shi=h0h,*slo=h0l; bf16 *dhi=h1h,*dlo=h1l;
    for(int l=0;l<4;l++){
        k_fwd<<<dim3(32,8),128,87040>>>(shi,slo);
        k_mixA<<<64,256>>>(wr+l*65536, wi+l*65536, ww+l*4096);
        k_layer<<<dim3(64,64),512,79872>>>(shi,slo,dhi,dlo,wb+l*64);
        const bf16* th=shi; const bf16* tl=slo;
        shi=dhi; slo=dlo; dhi=(bf16*)th; dlo=(bf16*)tl;
    }
    k_proj<<<16384,256>>>(shi,slo,qw,qb,out);
}

// round 17
// speedup vs baseline: 1.3314x; 1.0663x over previous
#include <cuda_runtime.h>
#include <cuda_bf16.h>
#include <cstdint>

#define NPTS 8192
#define HSIZE (64*NPTS*64)      // [b][n][i] elems = 33.5M
typedef unsigned int u32; typedef unsigned short u16; typedef __nv_bfloat16 bf16;

// ---- device scratch ----
__device__ bf16 g_h0hi[HSIZE], g_h0lo[HSIZE], g_h1hi[HSIZE], g_h1lo[HSIZE];
__device__ bf16 g_bash[32*NPTS], g_basl[32*NPTS];    // [freq r][pos]  r<16 cos, r>=16 sin
__device__ bf16 g_basTh[NPTS*32], g_basTl[NPTS*32];  // [pos][r]
__device__ float g_Fp[16*4096*32];
__device__ u16 g_Ah[64*64*96], g_Al[64*64*96];       // per-batch A [o][96]

__device__ __forceinline__ float gelu_exact(float v){ return 0.5f*v*(1.0f+erff(v*0.7071067811865476f)); }
__device__ __forceinline__ void split_bf(float v, u16& h, u16& l){
    bf16 bh=__float2bfloat16(v); bf16 bl=__float2bfloat16(v-__bfloat162float(bh));
    h=__bfloat16_as_ushort(bh); l=__bfloat16_as_ushort(bl);
}
__device__ __forceinline__ void mma_bf16(float* d, const u32* a, u32 b0, u32 b1){
    asm volatile("mma.sync.aligned.m16n8k16.row.col.f32.bf16.bf16.f32 "
        "{%0,%1,%2,%3}, {%4,%5,%6,%7}, {%8,%9}, {%0,%1,%2,%3};"
        : "+f"(d[0]),"+f"(d[1]),"+f"(d[2]),"+f"(d[3])
        : "r"(a[0]),"r"(a[1]),"r"(a[2]),"r"(a[3]),"r"(b0),"r"(b1));
}
__device__ __forceinline__ u32 sptr(const void* p){ return (u32)__cvta_generic_to_shared(p); }
__device__ __forceinline__ void ldsm4(u32* r, u32 a){
    asm volatile("ldmatrix.sync.aligned.m8n8.x4.shared.b16 {%0,%1,%2,%3}, [%4];"
        : "=r"(r[0]),"=r"(r[1]),"=r"(r[2]),"=r"(r[3]) : "r"(a));
}

// ---- init: basis tables (blocks 0..1023) + lifting (blocks 1024..) ----
__global__ void k_init(const float* __restrict__ x, const float* __restrict__ pw,
                       const float* __restrict__ pb){
    if(blockIdx.x < 1024){
        int idx=blockIdx.x*256+threadIdx.x;          // < 32*8192
        int r=idx>>13, n=idx&(NPTS-1), k=r&15;
        int rm=(k*n)&(NPTS-1);
        float a=(float)rm*(1.f/4096.f); float s,c; sincospif(a,&s,&c);
        float v=(r<16)?c:s;
        u16 hb,lb; split_bf(v,hb,lb);
        g_bash[r*NPTS+n]=__ushort_as_bfloat16(hb);  g_basl[r*NPTS+n]=__ushort_as_bfloat16(lb);
        g_basTh[n*32+r]=__ushort_as_bfloat16(hb);   g_basTl[n*32+r]=__ushort_as_bfloat16(lb);
    } else {
        int idx=(blockIdx.x-1024)*256+threadIdx.x;   // < HSIZE
        int b=idx>>19, n=(idx>>6)&(NPTS-1), i=idx&63;
        float v = x[(b<<13)|n]*pw[2*i] + ((float)n*(1.f/8191.f))*pw[2*i+1] + pb[i];
        u16 hb,lb; split_bf(v,hb,lb);
        g_h0hi[idx]=__ushort_as_bfloat16(hb); g_h0lo[idx]=__ushort_as_bfloat16(lb);
    }
}

// ---- forward DFT: 256 thr, 8 warps x m16, KSPLIT=16 (4 chunks of 128 n each) ----
#define FW_A2H 0
#define FW_A2L 17408
#define FW_BH  34816
#define FW_BL  39168
__global__ void __launch_bounds__(256) k_fwd(const bf16* __restrict__ hhi, const bf16* __restrict__ hlo){
    extern __shared__ u16 smu[];
    const int tid=threadIdx.x, lane=tid&31, wid=tid>>5;
    const int gid=lane>>2, tid4=lane&3;
    const int mb=blockIdx.x, split=blockIdx.y;
    float acc[4][4];
#pragma unroll
    for(int x=0;x<4;x++) for(int c=0;c<4;c++) acc[x][c]=0.f;
    for(int ch=0;ch<4;ch++){
        int nwin=split*512+ch*128;
        for(int it=0;it<2;it++){
            int pp=it*32+(tid>>3), iblk=tid&7;
#pragma unroll
            for(int bl=0;bl<2;bl++){
                size_t base=((size_t)(mb*2+bl)*NPTS + nwin + pp*2)*64 + iblk*8;
                uint4 q0=*(const uint4*)(hhi+base); uint4 q1=*(const uint4*)(hhi+base+64);
                u16 e0[8],e1[8]; *(uint4*)e0=q0; *(uint4*)e1=q1;
                u32* dst=(u32*)(smu+FW_A2H)+pp*136+bl*64+iblk*8;
#pragma unroll
                for(int j=0;j<8;j++) dst[j]=(u32)e0[j]|((u32)e1[j]<<16);
                q0=*(const uint4*)(hlo+base); q1=*(const uint4*)(hlo+base+64);
                *(uint4*)e0=q0; *(uint4*)e1=q1;
                dst=(u32*)(smu+FW_A2L)+pp*136+bl*64+iblk*8;
#pragma unroll
                for(int j=0;j<8;j++) dst[j]=(u32)e0[j]|((u32)e1[j]<<16);
            }
        }
        for(int e=tid;e<512;e+=256){
            int f=e>>4, blk=e&15;
            *(uint4*)(smu+FW_BH+f*136+blk*8)=*(const uint4*)((const u16*)g_bash+f*NPTS+nwin+blk*8);
            *(uint4*)(smu+FW_BL+f*136+blk*8)=*(const uint4*)((const u16*)g_basl+f*NPTS+nwin+blk*8);
        }
        __syncthreads();
        const int m0=wid*16;
        const u32* A2h=(const u32*)(smu+FW_A2H);
        const u32* A2l=(const u32*)(smu+FW_A2L);
        for(int ks=0;ks<8;ks++){
            int k0=ks*16, p=k0/2+tid4;
            u32 ah[4], al[4];
            {
                int m=m0+gid;
                ah[0]=A2h[p*136+m];     ah[1]=A2h[p*136+m+8];
                ah[2]=A2h[(p+4)*136+m]; ah[3]=A2h[(p+4)*136+m+8];
                al[0]=A2l[p*136+m];     al[1]=A2l[p*136+m+8];
                al[2]=A2l[(p+4)*136+m]; al[3]=A2l[(p+4)*136+m+8];
            }
#pragma unroll
            for(int nt=0;nt<4;nt++){
                int rb=(nt*8+gid)*136+k0+tid4*2;
                u32 bh0=*(const u32*)(smu+FW_BH+rb), bh1=*(const u32*)(smu+FW_BH+rb+8);
                u32 bl0=*(const u32*)(smu+FW_BL+rb), bl1=*(const u32*)(smu+FW_BL+rb+8);
                mma_bf16(acc[nt],ah,bh0,bh1);
                mma_bf16(acc[nt],ah,bl0,bl1);
                mma_bf16(acc[nt],al,bh0,bh1);
            }
        }
        __syncthreads();
    }
    int row=mb*128+wid*16+gid;
    float* dp=g_Fp+(size_t)split*131072+(size_t)row*32;
#pragma unroll
    for(int nt=0;nt<4;nt++){
        int col=nt*8+tid4*2;
        *(float2*)(dp+col)=make_float2(acc[nt][0],acc[nt][1]);
        *(float2*)(dp+8*32+col)=make_float2(acc[nt][2],acc[nt][3]);
    }
}

// ---- merged: reduce F partials + mode mix + build A  (CTA = batch) ----
__global__ void __launch_bounds__(256) k_mixA(const float* __restrict__ wr, const float* __restrict__ wi,
                                              const float* __restrict__ ww){
    __shared__ float Fs[64][32];
    __shared__ float Gs[2][16][64];
    const int b=blockIdx.x, tid=threadIdx.x;
#pragma unroll
    for(int t=0;t<8;t++){
        int e=tid+t*256;
        float s=0.f;
#pragma unroll
        for(int p=0;p<16;p++) s+=g_Fp[p*131072 + b*2048 + e];
        Fs[e>>5][e&31]=s;
    }
    __syncthreads();
    const int k=tid&15, og=tid>>4;
#pragma unroll
    for(int rep=0;rep<4;rep++){
        int o=og+rep*16;
        float gre=0.f,gim=0.f;
#pragma unroll 8
        for(int i=0;i<64;i++){
            float fr=Fs[i][k], S=Fs[i][16+k];
            float wrv=wr[(i*64+o)*16+k], wiv=wi[(i*64+o)*16+k];
            gre+=fr*wrv+S*wiv; gim+=fr*wiv-S*wrv;
        }
        float sc=(k==0?1.0f:2.0f)*(1.0f/(float)NPTS);
        Gs[0][k][o]=gre*sc;
        Gs[1][k][o]=gim*sc;
    }
    __syncthreads();
    for(int t=tid;t<6144;t+=256){
        int o=t/96, c=t%96;
        float v;
        if(c<64) v=ww[o*64+c];
        else if(c<80) v= Gs[0][c-64][o];
        else          v=-Gs[1][c-80][o];
        u16 hb,lb; split_bf(v,hb,lb);
        g_Ah[b*6144+t]=hb; g_Al[b*6144+t]=lb;
    }
}

// ---- layer: n-tile 64, 512 thr, 16 warps x (m16 x n16), higher occupancy ----
#define LA_AH 0
#define LA_AL 6656
#define LA_BTH 13312
#define LA_BTL 19968
#define EP_BNH 0
#define EP_BNL 4608
__global__ void __launch_bounds__(512,3) k_layer(const bf16* __restrict__ shi, const bf16* __restrict__ slo,
                                                 bf16* __restrict__ dhi, bf16* __restrict__ dlo,
                                                 const float* __restrict__ wb){
    extern __shared__ __align__(16) u16 smu[];
    const int tid=threadIdx.x, lane=tid&31, wid=tid>>5;
    const int gid=lane>>2, tid4=lane&3;
    const int b=blockIdx.y, n0=blockIdx.x*64;
    {   // stage A  (rows 96 u16 = 12 uint4, 64 rows)
        const uint4* s0=(const uint4*)(g_Ah+b*6144);
        const uint4* s1=(const uint4*)(g_Al+b*6144);
        for(int e=tid;e<768;e+=512){
            int o=e/12, c=e%12;
            *(uint4*)(smu+LA_AH+o*104+c*8)=s0[e];
            *(uint4*)(smu+LA_AL+o*104+c*8)=s1[e];
        }
    }
    {   int e=tid;                  // BT h part (k 0..63): 512 uint4
        int n=e>>3, blk=e&7;
        size_t src=((size_t)b*NPTS+n0+n)*64+blk*8;
        *(uint4*)(smu+LA_BTH+n*104+blk*8)=*(const uint4*)(shi+src);
        *(uint4*)(smu+LA_BTL+n*104+blk*8)=*(const uint4*)(slo+src);
    }
    if(tid<256){                    // BT basis part (k 64..95): 256 uint4
        int n=tid>>2, blk=tid&3;
        *(uint4*)(smu+LA_BTH+n*104+64+blk*8)=*(const uint4*)((const u16*)g_basTh+(size_t)(n0+n)*32+blk*8);
        *(uint4*)(smu+LA_BTL+n*104+64+blk*8)=*(const uint4*)((const u16*)g_basTl+(size_t)(n0+n)*32+blk*8);
    }
    __syncthreads();
    const int m0=(wid&3)*16, nb0=(wid>>2)*16;
    float acc[2][4];
#pragma unroll
    for(int x=0;x<2;x++) for(int c=0;c<4;c++) acc[x][c]=0.f;
    const u32 S=sptr(smu);
    u32 aA =S+2u*(LA_AH + (m0+(lane&15))*104 + ((lane>>4)<<3));
    u32 aAl=S+2u*(LA_AL + (m0+(lane&15))*104 + ((lane>>4)<<3));
    {
        int brow=nb0+((lane>>4)<<3)+(lane&7), bcol=(lane&8);
        u32 aBh=S+2u*(LA_BTH+brow*104+bcol);
        u32 aBl=S+2u*(LA_BTL+brow*104+bcol);
#pragma unroll
        for(int ks=0;ks<6;ks++){
            u32 ah[4],al[4],bh[4],bl[4];
            ldsm4(ah,aA); ldsm4(al,aAl);
            ldsm4(bh,aBh); ldsm4(bl,aBl);
            mma_bf16(acc[0],ah,bh[0],bh[1]); mma_bf16(acc[0],ah,bl[0],bl[1]); mma_bf16(acc[0],al,bh[0],bh[1]);
            mma_bf16(acc[1],ah,bh[2],bh[3]); mma_bf16(acc[1],ah,bl[2],bl[3]); mma_bf16(acc[1],al,bh[2],bh[3]);
            aA+=32; aAl+=32; aBh+=32; aBl+=32;
        }
    }
    __syncthreads();   // reuse smem for bounce
    const int o0=m0+gid, o1=o0+8;
    float bb0=__ldg(wb+o0), bb1=__ldg(wb+o1);
#pragma unroll
    for(int nt=0;nt<2;nt++){
        int n=nb0+nt*8+tid4*2;
        float v0=gelu_exact(acc[nt][0]+bb0), v1=gelu_exact(acc[nt][1]+bb0);
        float v2=gelu_exact(acc[nt][2]+bb1), v3=gelu_exact(acc[nt][3]+bb1);
        u16 h0,l0,h1,l1,h2,l2,h3,l3;
        split_bf(v0,h0,l0); split_bf(v1,h1,l1); split_bf(v2,h2,l2); split_bf(v3,h3,l3);
        smu[EP_BNH+n*72+o0]=h0; smu[EP_BNH+(n+1)*72+o0]=h1;
        smu[EP_BNH+n*72+o1]=h2; smu[EP_BNH+(n+1)*72+o1]=h3;
        smu[EP_BNL+n*72+o0]=l0; smu[EP_BNL+(n+1)*72+o0]=l1;
        smu[EP_BNL+n*72+o1]=l2; smu[EP_BNL+(n+1)*72+o1]=l3;
    }
    __syncthreads();
    {   int e=tid;                  // coalesced global write [b][n][o]: 512 uint4
        int n=e>>3, blk=e&7;
        size_t dst=((size_t)b*NPTS+n0+n)*64+blk*8;
        *(uint4*)(dhi+dst)=*(const uint4*)(smu+EP_BNH+n*72+blk*8);
        *(uint4*)(dlo+dst)=*(const uint4*)(smu+EP_BNL+n*72+blk*8);
    }
}

// ---- projection ----
__global__ void k_proj(const bf16* __restrict__ hhi, const bf16* __restrict__ hlo,
                       const float* __restrict__ qw, const float* __restrict__ qb,
                       float* __restrict__ out){
    int t=threadIdx.x;
    int r=blockIdx.x*32 + (t>>3);
    int l8=t&7;
    size_t base=(size_t)r*64 + l8*8;
    float acc=0.f;
    uint4 qh=*(const uint4*)(hhi+base); uint4 ql=*(const uint4*)(hlo+base);
    u16 eh[8],el[8]; *(uint4*)eh=qh; *(uint4*)el=ql;
#pragma unroll
    for(int j=0;j<8;j++)
        acc += (__bfloat162float(__ushort_as_bfloat16(eh[j]))+__bfloat162float(__ushort_as_bfloat16(el[j])))*__ldg(qw+l8*8+j);
    acc += __shfl_down_sync(0xFFFFFFFFu,acc,4);
    acc += __shfl_down_sync(0xFFFFFFFFu,acc,2);
    acc += __shfl_down_sync(0xFFFFFFFFu,acc,1);
    if(l8==0) out[r]=acc+__ldg(qb);
}

// ---- launch ----
extern "C" void kernel_launch(void* const* d_in, const int* in_sizes, int n_in,
                              void* d_out, int out_size){
    const float* x =(const float*)d_in[0];
    const float* pw=(const float*)d_in[1];
    const float* pb=(const float*)d_in[2];
    const float* wr=(const float*)d_in[3];
    const float* wi=(const float*)d_in[4];
    const float* ww=(const float*)d_in[5];
    const float* wb=(const float*)d_in[6];
    const float* qw=(const float*)d_in[7];
    const float* qb=(const float*)d_in[8];
    float* out=(float*)d_out;

    bf16 *h0h,*h0l,*h1h,*h1l;
    cudaGetSymbolAddress((void**)&h0h,g_h0hi); cudaGetSymbolAddress((void**)&h0l,g_h0lo);
    cudaGetSymbolAddress((void**)&h1h,g_h1hi); cudaGetSymbolAddress((void**)&h1l,g_h1lo);

    cudaFuncSetAttribute(k_fwd,  cudaFuncAttributeMaxDynamicSharedMemorySize, 87040);
    cudaFuncSetAttribute(k_layer,cudaFuncAttributeMaxDynamicSharedMemorySize, 53248);

    k_init<<<1024 + HSIZE/256, 256>>>(x,pw,pb);

    const bf16 *shi=h0h,*slo=h0l; bf16 *dhi=h1h,*dlo=h1l;
    for(int l=0;l<4;l++){
        k_fwd<<<dim3(32,16),256,87040>>>(shi,slo);
        k_mixA<<<64,256>>>(wr+l*65536, wi+l*65536, ww+l*4096);
        k_layer<<<dim3(128,64),512,53248>>>(shi,slo,dhi,dlo,wb+l*64);
        const bf16* th=shi; const bf16* tl=slo;
        shi=dhi; slo=dlo; dhi=(bf16*)th; dlo=(bf16*)tl;
    }
    k_proj<<<16384,256>>>(shi,slo,qw,qb,out);
}